// round 8
// baseline (speedup 1.0000x reference)
#include <cuda_runtime.h>
#include <cuda_bf16.h>
#include <math.h>
#include <stdint.h>

#define BB 128
#define NN 49
#define CC 2048
#define DD 512
#define EE 512
#define VOC 10000
#define TT 20
#define RR (TT * BB)

typedef __nv_bfloat16 bf16;
typedef __nv_bfloat162 bf162;

// ---------------- fp32 scratch ----------------
__device__ float g_Vf[BB * NN * DD];
__device__ float g_zbase[BB * NN * NN];
__device__ float g_bcat[3 * DD];
__device__ float g_init[BB * 3 * DD];
__device__ float g_vg[BB * DD];
__device__ float g_m[BB * DD];
__device__ float g_tm[RR * DD];
__device__ float g_bsum[4 * DD];
__device__ float g_xg[RR * 4 * DD];
__device__ float g_xx[RR * DD];
__device__ float g_G1[RR * DD];
__device__ float g_H[RR * DD];
__device__ float g_s[RR * DD];
__device__ float g_gH[RR * NN];
__device__ float g_sWs[RR * NN];
__device__ float g_out[RR * DD];
__device__ float g_logits[(size_t)RR * VOC];
__device__ int   g_bar[32];

// ---------------- bf16 scratch ----------------
__device__ __align__(16) bf16 g_image_bf[BB * NN * CC];
__device__ __align__(16) bf16 g_Wa_bf[DD * CC];
__device__ __align__(16) bf16 g_mean_bf[BB * CC];
__device__ __align__(16) bf16 g_Wcat_bf[3 * DD * CC];
__device__ __align__(16) bf16 g_xcat_bf[RR * (DD + EE)];
__device__ __align__(16) bf16 g_Wih_bf[4 * DD * (DD + EE)];
__device__ __align__(16) bf16 g_Wx_bf[DD * (DD + EE)];
__device__ __align__(16) bf16 g_Whh_bf[4 * DD * DD];
__device__ __align__(16) bf16 g_Wh2_bf[DD * DD];
__device__ __align__(16) bf16 g_WH_bf[DD * DD];
__device__ __align__(16) bf16 g_Wc_bf[DD * DD];
__device__ __align__(16) bf16 g_Wfc_bf[DD * DD];
__device__ __align__(16) bf16 g_Wp_bf[VOC * DD];
__device__ __align__(16) bf16 g_Wg_bf[NN * DD];
__device__ __align__(16) bf16 g_Ws_bf[NN * DD];
__device__ __align__(16) bf16 g_hseq_bf[(TT + 1) * BB * DD];
__device__ __align__(16) bf16 g_a_bf[RR * DD];
__device__ __align__(16) bf16 g_ctxH_bf[RR * DD];
__device__ __align__(16) bf16 g_out_bf[RR * DD];
__device__ __align__(16) bf16 g_Vfb[BB * NN * DD];
__device__ __align__(16) bf16 g_H_bf[RR * DD];
__device__ __align__(16) bf16 g_s_bf[RR * DD];

__device__ __forceinline__ float sigmoidf_(float x) { return 1.f / (1.f + expf(-x)); }

__device__ __forceinline__ uint32_t smem_u32(const void* p) {
    uint32_t a;
    asm("{ .reg .u64 t; cvta.to.shared.u64 t, %1; cvt.u32.u64 %0, t; }" : "=r"(a) : "l"(p));
    return a;
}

__device__ __forceinline__ void cp_async16(uint32_t dst, const void* src, bool pred) {
    int sz = pred ? 16 : 0;
    asm volatile("cp.async.cg.shared.global [%0], [%1], 16, %2;"
                 :: "r"(dst), "l"(src), "r"(sz) : "memory");
}
#define CP_COMMIT() asm volatile("cp.async.commit_group;" ::: "memory")
#define CP_WAIT1()  asm volatile("cp.async.wait_group 1;" ::: "memory")
#define CP_WAIT0()  asm volatile("cp.async.wait_group 0;" ::: "memory")

__device__ __forceinline__ void mma_bf16(float* c, const uint32_t* a, uint32_t b0, uint32_t b1)
{
    asm volatile(
        "mma.sync.aligned.m16n8k16.row.col.f32.bf16.bf16.f32 "
        "{%0,%1,%2,%3}, {%4,%5,%6,%7}, {%8,%9}, {%0,%1,%2,%3};"
        : "+f"(c[0]), "+f"(c[1]), "+f"(c[2]), "+f"(c[3])
        : "r"(a[0]), "r"(a[1]), "r"(a[2]), "r"(a[3]), "r"(b0), "r"(b1));
}

#define ASTR 40
#define ABUF (128 * ASTR)
#define SMEM_MM (4 * ABUF * 2)

// ==================== generic bf16 HMMA GEMM ====================
__global__ void __launch_bounds__(256, 2) gemm_bf(
    const bf16* __restrict__ A, int lda,
    const bf16* __restrict__ B, int ldb,
    const float* __restrict__ bias,
    float* __restrict__ C, bf16* __restrict__ Cb, int ldc,
    int N, int K, int act)
{
    extern __shared__ bf16 sm[];
    bf16* sA[2] = { sm, sm + ABUF };
    bf16* sB[2] = { sm + 2 * ABUF, sm + 3 * ABUF };
    const uint32_t sA_u[2] = { smem_u32(sA[0]), smem_u32(sA[1]) };
    const uint32_t sB_u[2] = { smem_u32(sB[0]), smem_u32(sB[1]) };

    const int tid = threadIdx.x;
    const int wid = tid >> 5, lane = tid & 31;
    const int g = lane >> 2, tg = lane & 3;
    const int wm = (wid & 3) * 32;
    const int wn = (wid >> 2) * 64;
    const int m0 = blockIdx.y * 128;
    const int n0 = blockIdx.x * 128;

    A += (size_t)m0 * lda;

    float acc[2][8][4];
#pragma unroll
    for (int mi = 0; mi < 2; mi++)
#pragma unroll
        for (int ni = 0; ni < 8; ni++)
#pragma unroll
            for (int q = 0; q < 4; q++) acc[mi][ni][q] = 0.f;

    const int KI = K >> 5;
    const int r_ld = tid >> 2;
    const int c16 = tid & 3;

    {
#pragma unroll
        for (int j = 0; j < 2; j++) {
            int row = r_ld + j * 64;
            cp_async16(sA_u[0] + (row * ASTR + c16 * 8) * 2,
                       A + (size_t)row * lda + c16 * 8, true);
        }
#pragma unroll
        for (int j = 0; j < 2; j++) {
            int row = r_ld + j * 64;
            int gn = n0 + row;
            bool ok = gn < N;
            int gs = ok ? gn : (N - 1);
            cp_async16(sB_u[0] + (row * ASTR + c16 * 8) * 2,
                       B + (size_t)gs * ldb + c16 * 8, ok);
        }
        CP_COMMIT();
    }

    for (int i = 0; i < KI; i++) {
        const int cur = i & 1;
        if (i + 1 < KI) {
            const int nxt = cur ^ 1;
            const int k0 = (i + 1) << 5;
#pragma unroll
            for (int j = 0; j < 2; j++) {
                int row = r_ld + j * 64;
                cp_async16(sA_u[nxt] + (row * ASTR + c16 * 8) * 2,
                           A + (size_t)row * lda + k0 + c16 * 8, true);
            }
#pragma unroll
            for (int j = 0; j < 2; j++) {
                int row = r_ld + j * 64;
                int gn = n0 + row;
                bool ok = gn < N;
                int gs = ok ? gn : (N - 1);
                cp_async16(sB_u[nxt] + (row * ASTR + c16 * 8) * 2,
                           B + (size_t)gs * ldb + k0 + c16 * 8, ok);
            }
        }
        CP_COMMIT();
        CP_WAIT1();
        __syncthreads();

        const uint32_t* As_ = reinterpret_cast<const uint32_t*>(sA[cur]);
        const uint32_t* Bs_ = reinterpret_cast<const uint32_t*>(sB[cur]);
#pragma unroll
        for (int kk = 0; kk < 2; kk++) {
            const int kw = kk * 8;
            uint32_t a[2][4];
#pragma unroll
            for (int mi = 0; mi < 2; mi++) {
                int r = wm + mi * 16 + g;
                a[mi][0] = As_[r * 20 + kw + tg];
                a[mi][1] = As_[(r + 8) * 20 + kw + tg];
                a[mi][2] = As_[r * 20 + kw + 4 + tg];
                a[mi][3] = As_[(r + 8) * 20 + kw + 4 + tg];
            }
#pragma unroll
            for (int ni = 0; ni < 8; ni++) {
                int rn = wn + ni * 8 + g;
                uint32_t b0 = Bs_[rn * 20 + kw + tg];
                uint32_t b1 = Bs_[rn * 20 + kw + 4 + tg];
                mma_bf16(acc[0][ni], a[0], b0, b1);
                mma_bf16(acc[1][ni], a[1], b0, b1);
            }
        }
        __syncthreads();
    }

#pragma unroll
    for (int mi = 0; mi < 2; mi++) {
#pragma unroll
        for (int ni = 0; ni < 8; ni++) {
            int gr = m0 + wm + mi * 16 + g;
            int gc = n0 + wn + ni * 8 + 2 * tg;
#pragma unroll
            for (int q = 0; q < 4; q++) {
                int r = gr + (q >> 1) * 8;
                int c = gc + (q & 1);
                if (c < N) {
                    float v = acc[mi][ni][q];
                    if (bias) v += bias[c];
                    if (act == 1) v = fmaxf(v, 0.f);
                    else if (act == 2) v = tanhf(v);
                    C[(size_t)r * ldc + c] = v;
                    if (Cb) Cb[(size_t)r * ldc + c] = __float2bfloat16_rn(v);
                }
            }
        }
    }
}

// ==================== persistent LSTM recurrence ====================
// 16 CTAs. CTA i owns d-range [32i, 32i+32): its 128 SMEM weight rows are
// Whh rows { gate*512 + d : gate in 0..3, d in d-range }. All 4 gates of the
// CTA's d-slice land in its own 128-wide MMA tile -> local elementwise,
// one grid barrier per step (h exchange only).
#define LCHUNK (128 * ASTR * 2)              // 10240 B per 128x32 bf16 chunk
#define LW_BYTES (16 * LCHUNK)               // 163840 B resident Whh slice
#define LGSTR 132
#define LG_BYTES (128 * LGSTR * 4)           // 67584 B gates exchange tile
#define LSTM_SMEM (LW_BYTES + LG_BYTES)      // 231424 B (h bufs overlap gates)

__global__ void __launch_bounds__(256, 1) lstm_persistent(
    const bf16* __restrict__ Whh,   // [2048,512] bf16
    const float* __restrict__ xg,   // [T*128,2048] incl biases
    float* __restrict__ m,          // [128,512]
    bf16* __restrict__ hseq,        // [(T+1)*128,512]
    float* __restrict__ tmv)        // [T*128,512]
{
    extern __shared__ char smemc[];
    const uint32_t sb = smem_u32(smemc);
    const uint32_t hbuf_u[2] = { sb + LW_BYTES, sb + LW_BYTES + LCHUNK };
    float* sG = reinterpret_cast<float*>(smemc + LW_BYTES);

    const int tid = threadIdx.x;
    const int wid = tid >> 5, lane = tid & 31;
    const int g = lane >> 2, tg = lane & 3;
    const int wm = (wid & 3) * 32;
    const int wn = (wid >> 2) * 64;
    const int d0 = blockIdx.x * 32;
    const int r_ld = tid >> 2;
    const int c16 = tid & 3;

    // ---- load resident Whh slice (once) ----
    for (int c = 0; c < 16; c++) {
        const int k0 = c << 5;
#pragma unroll
        for (int j = 0; j < 2; j++) {
            int row = r_ld + j * 64;                       // n_local
            int grow = (row >> 5) * DD + d0 + (row & 31);  // global Whh row
            cp_async16(sb + c * LCHUNK + (row * ASTR + c16 * 8) * 2,
                       Whh + (size_t)grow * DD + k0 + c16 * 8, true);
        }
    }
    CP_COMMIT();
    CP_WAIT0();
    __syncthreads();

    for (int t = 0; t < TT; t++) {
        const bf16* A = hseq + (size_t)t * BB * DD;

        float acc[2][8][4];
#pragma unroll
        for (int mi = 0; mi < 2; mi++)
#pragma unroll
            for (int ni = 0; ni < 8; ni++)
#pragma unroll
                for (int q = 0; q < 4; q++) acc[mi][ni][q] = 0.f;

        // prologue: h chunk 0
#pragma unroll
        for (int j = 0; j < 2; j++) {
            int row = r_ld + j * 64;
            cp_async16(hbuf_u[0] + (row * ASTR + c16 * 8) * 2,
                       A + (size_t)row * DD + c16 * 8, true);
        }
        CP_COMMIT();

        for (int i = 0; i < 16; i++) {
            const int cur = i & 1;
            if (i + 1 < 16) {
                const int k0 = (i + 1) << 5;
#pragma unroll
                for (int j = 0; j < 2; j++) {
                    int row = r_ld + j * 64;
                    cp_async16(hbuf_u[cur ^ 1] + (row * ASTR + c16 * 8) * 2,
                               A + (size_t)row * DD + k0 + c16 * 8, true);
                }
            }
            CP_COMMIT();
            CP_WAIT1();
            __syncthreads();

            const uint32_t* As_ = reinterpret_cast<const uint32_t*>(smemc + LW_BYTES + cur * LCHUNK);
            const uint32_t* Bs_ = reinterpret_cast<const uint32_t*>(smemc + i * LCHUNK);
#pragma unroll
            for (int kk = 0; kk < 2; kk++) {
                const int kw = kk * 8;
                uint32_t a[2][4];
#pragma unroll
                for (int mi = 0; mi < 2; mi++) {
                    int r = wm + mi * 16 + g;
                    a[mi][0] = As_[r * 20 + kw + tg];
                    a[mi][1] = As_[(r + 8) * 20 + kw + tg];
                    a[mi][2] = As_[r * 20 + kw + 4 + tg];
                    a[mi][3] = As_[(r + 8) * 20 + kw + 4 + tg];
                }
#pragma unroll
                for (int ni = 0; ni < 8; ni++) {
                    int rn = wn + ni * 8 + g;
                    uint32_t b0 = Bs_[rn * 20 + kw + tg];
                    uint32_t b1 = Bs_[rn * 20 + kw + 4 + tg];
                    mma_bf16(acc[0][ni], a[0], b0, b1);
                    mma_bf16(acc[1][ni], a[1], b0, b1);
                }
            }
            __syncthreads();
        }
        CP_WAIT0();
        __syncthreads();   // h bufs dead; sG may overwrite

        // stage gates tile to SMEM: sG[batch_row][n_local]
#pragma unroll
        for (int mi = 0; mi < 2; mi++)
#pragma unroll
            for (int ni = 0; ni < 8; ni++) {
                int gr = wm + mi * 16 + g;
                int gc = wn + ni * 8 + 2 * tg;
#pragma unroll
                for (int q = 0; q < 4; q++)
                    sG[(gr + (q >> 1) * 8) * LGSTR + gc + (q & 1)] = acc[mi][ni][q];
            }
        __syncthreads();

        // local LSTM elementwise for d-range [d0, d0+32)
        const float* xr = xg + (size_t)t * BB * 4 * DD;
        bf16* hn = hseq + (size_t)(t + 1) * BB * DD;
        float* tmo = tmv + (size_t)t * BB * DD;
#pragma unroll
        for (int e = tid; e < 128 * 32; e += 256) {
            int row = e >> 5, dl = e & 31;
            int d = d0 + dl;
            const float* x = xr + (size_t)row * (4 * DD);
            float gi = sG[row * LGSTR + dl]      + x[d];
            float gf = sG[row * LGSTR + 32 + dl] + x[DD + d];
            float gg = sG[row * LGSTR + 64 + dl] + x[2 * DD + d];
            float go = sG[row * LGSTR + 96 + dl] + x[3 * DD + d];
            size_t idx = (size_t)row * DD + d;
            float m2 = sigmoidf_(gf) * m[idx] + sigmoidf_(gi) * tanhf(gg);
            float tm2 = tanhf(m2);
            m[idx] = m2;
            hn[idx] = __float2bfloat16_rn(sigmoidf_(go) * tm2);
            tmo[idx] = tm2;
        }
        __syncthreads();   // all reads of sG done before next-step h prefetch

        // grid barrier: h_{t+1} visible to all CTAs
        if (tid == 0) {
            __threadfence();
            atomicAdd(&g_bar[t], 1);
            volatile int* vb = g_bar;
            while (vb[t] < 16) { }
            __threadfence();
        }
        __syncthreads();
    }
}

__global__ void bar_reset()
{
    if (threadIdx.x < 32) g_bar[threadIdx.x] = 0;
}

// ==================== SIMT GEMM (zbase only) ====================
template <int BM, int BN, int BK, int TM, int TN>
__global__ void gemm_nt(const float* __restrict__ A, int lda,
                        const float* __restrict__ Bm, int ldb,
                        float* __restrict__ C, int ldc,
                        int M, int N, int K,
                        long long sA, long long sB, long long sC)
{
    constexpr int THREADS = (BM / TM) * (BN / TN);
    __shared__ float As[BK][BM + 4];
    __shared__ float Bs[BK][BN + 4];

    A += (long long)blockIdx.z * sA;
    Bm += (long long)blockIdx.z * sB;
    C += (long long)blockIdx.z * sC;

    const int tid = threadIdx.x;
    const int bm0 = blockIdx.y * BM;
    const int bn0 = blockIdx.x * BN;
    const int tm = (tid / (BN / TN)) * TM;
    const int tn = (tid % (BN / TN)) * TN;

    float acc[TM][TN];
#pragma unroll
    for (int i = 0; i < TM; i++)
#pragma unroll
        for (int j = 0; j < TN; j++) acc[i][j] = 0.f;

    for (int k0 = 0; k0 < K; k0 += BK) {
#pragma unroll
        for (int i = tid; i < BM * (BK / 4); i += THREADS) {
            int row = i / (BK / 4);
            int kc = i % (BK / 4);
            int gm = bm0 + row;
            int gk = k0 + kc * 4;
            float4 v = make_float4(0.f, 0.f, 0.f, 0.f);
            if (gm < M) v = *reinterpret_cast<const float4*>(A + (size_t)gm * lda + gk);
            As[kc * 4 + 0][row] = v.x; As[kc * 4 + 1][row] = v.y;
            As[kc * 4 + 2][row] = v.z; As[kc * 4 + 3][row] = v.w;
        }
#pragma unroll
        for (int i = tid; i < BN * (BK / 4); i += THREADS) {
            int row = i / (BK / 4);
            int kc = i % (BK / 4);
            int gn = bn0 + row;
            int gk = k0 + kc * 4;
            float4 v = make_float4(0.f, 0.f, 0.f, 0.f);
            if (gn < N) v = *reinterpret_cast<const float4*>(Bm + (size_t)gn * ldb + gk);
            Bs[kc * 4 + 0][row] = v.x; Bs[kc * 4 + 1][row] = v.y;
            Bs[kc * 4 + 2][row] = v.z; Bs[kc * 4 + 3][row] = v.w;
        }
        __syncthreads();
#pragma unroll
        for (int k = 0; k < BK; k++) {
            float ra[TM], rb[TN];
#pragma unroll
            for (int i = 0; i < TM; i++) ra[i] = As[k][tm + i];
#pragma unroll
            for (int j = 0; j < TN; j++) rb[j] = Bs[k][tn + j];
#pragma unroll
            for (int i = 0; i < TM; i++)
#pragma unroll
                for (int j = 0; j < TN; j++) acc[i][j] += ra[i] * rb[j];
        }
        __syncthreads();
    }

#pragma unroll
    for (int i = 0; i < TM; i++) {
        int gm = bm0 + tm + i;
        if (gm >= M) continue;
#pragma unroll
        for (int j = 0; j < TN; j++) {
            int gn = bn0 + tn + j;
            if (gn >= N) continue;
            C[(size_t)gm * ldc + gn] = acc[i][j];
        }
    }
}

// ==================== small kernels ====================
__global__ void f2bf(const float* __restrict__ in, bf16* __restrict__ out, int n4)
{
    int i = blockIdx.x * blockDim.x + threadIdx.x;
    if (i >= n4) return;
    float4 v = reinterpret_cast<const float4*>(in)[i];
    bf162* o = reinterpret_cast<bf162*>(out) + i * 2;
    o[0] = __floats2bfloat162_rn(v.x, v.y);
    o[1] = __floats2bfloat162_rn(v.z, v.w);
}

__global__ void mean_kernel(const float* __restrict__ x, bf16* __restrict__ mean_bf)
{
    int idx = blockIdx.x * blockDim.x + threadIdx.x;
    if (idx >= BB * CC) return;
    int b = idx / CC, c = idx % CC;
    float acc = 0.f;
    const float* p = x + (size_t)b * NN * CC + c;
#pragma unroll 7
    for (int n = 0; n < NN; n++) acc += p[(size_t)n * CC];
    mean_bf[idx] = __float2bfloat16_rn(acc * (1.f / (float)NN));
}

__global__ void cat_w3(const float* __restrict__ Wb, const float* __restrict__ Whi,
                       const float* __restrict__ Wmi, bf16* __restrict__ Wcat)
{
    int idx = blockIdx.x * blockDim.x + threadIdx.x;
    if (idx >= 3 * DD * CC) return;
    int r = idx / CC;
    const float* src = (r < DD) ? Wb : (r < 2 * DD) ? Whi : Wmi;
    int rr = (r < DD) ? r : (r < 2 * DD) ? r - DD : r - 2 * DD;
    Wcat[idx] = __float2bfloat16_rn(src[(size_t)rr * CC + (idx % CC)]);
}

__global__ void cat_bias3(const float* __restrict__ bb, const float* __restrict__ bhi,
                          const float* __restrict__ bmi, float* __restrict__ bcat)
{
    int i = blockIdx.x * blockDim.x + threadIdx.x;
    if (i >= 3 * DD) return;
    bcat[i] = (i < DD) ? bb[i] : (i < 2 * DD) ? bhi[i - DD] : bmi[i - 2 * DD];
}

__global__ void split_init(float* __restrict__ vg, bf16* __restrict__ h0,
                           float* __restrict__ m0)
{
    int idx = blockIdx.x * blockDim.x + threadIdx.x;
    if (idx >= BB * DD) return;
    int b = idx >> 9, d = idx & (DD - 1);
    const float* row = g_init + (size_t)b * (3 * DD);
    vg[idx] = row[d];
    h0[idx] = __float2bfloat16_rn(row[DD + d]);
    m0[idx] = row[2 * DD + d];
}

__global__ void xcat_build(const int* __restrict__ target, const float* __restrict__ emb)
{
    int idx = blockIdx.x * blockDim.x + threadIdx.x;
    if (idx >= RR * (DD + EE)) return;
    int c = idx & 1023;
    int r = idx >> 10;
    int b = r % BB, t = r / BB;
    float v;
    if (c < DD) {
        v = g_vg[(size_t)b * DD + c];
    } else {
        v = 0.f;
        if (t > 0) v = emb[(size_t)target[b * TT + (t - 1)] * EE + (c - DD)];
    }
    g_xcat_bf[idx] = __float2bfloat16_rn(v);
}

__global__ void bias_sum(const float* __restrict__ bih, const float* __restrict__ bhh)
{
    int i = blockIdx.x * blockDim.x + threadIdx.x;
    if (i < 4 * DD) g_bsum[i] = bih[i] + bhh[i];
}

__global__ void gate_a()
{
    int idx = blockIdx.x * blockDim.x + threadIdx.x;
    if (idx >= RR * DD) return;
    g_a_bf[idx] = __float2bfloat16_rn(sigmoidf_(g_xx[idx] + g_G1[idx]) * g_tm[idx]);
}

__global__ void attn_batched(const float* __restrict__ wh, float* __restrict__ out_attn)
{
    int r = blockIdx.x;
    int t = r / BB, b = r % BB;
    int tid = threadIdx.x;
    __shared__ float gHs[NN], whs[NN], zs[NN + 1], alphas[NN + 1];
    if (tid < NN) { gHs[tid] = g_gH[(size_t)r * NN + tid]; whs[tid] = wh[tid]; }
    __syncthreads();

    if (tid < NN) {
        const float* zb = g_zbase + ((size_t)b * NN + tid) * NN;
        float acc = 0.f;
        for (int k = 0; k < NN; k++) acc += tanhf(zb[k] + gHs[k]) * whs[k];
        zs[tid] = acc;
    } else if (tid == NN) {
        const float* sw = g_sWs + (size_t)r * NN;
        float acc = 0.f;
        for (int k = 0; k < NN; k++) acc += tanhf(sw[k] + gHs[k]) * whs[k];
        zs[NN] = acc;
    }
    __syncthreads();

    if (tid == 0) {
        float mx = -1e30f;
        for (int i = 0; i <= NN; i++) mx = fmaxf(mx, zs[i]);
        float sum = 0.f;
        for (int i = 0; i <= NN; i++) { float e = expf(zs[i] - mx); alphas[i] = e; sum += e; }
        float inv = 1.f / sum;
        for (int i = 0; i <= NN; i++) alphas[i] *= inv;
    }
    __syncthreads();

    if (tid < NN) out_attn[((size_t)b * TT + t) * NN + tid] = alphas[tid];

    {
        int d = tid * 2;
        float aN = alphas[NN];
        float cx = aN * g_s[(size_t)r * DD + d];
        float cy = aN * g_s[(size_t)r * DD + d + 1];
        const bf162* vf = reinterpret_cast<const bf162*>(g_Vfb + (size_t)b * NN * DD + d);
#pragma unroll 7
        for (int n = 0; n < NN; n++) {
            float2 v = __bfloat1622float2(vf[n * (DD / 2)]);
            cx += alphas[n] * v.x;
            cy += alphas[n] * v.y;
        }
        cx += g_H[(size_t)r * DD + d];
        cy += g_H[(size_t)r * DD + d + 1];
        reinterpret_cast<bf162*>(g_ctxH_bf + (size_t)r * DD + d)[0] =
            __floats2bfloat162_rn(cx, cy);
    }
}

__global__ void logsoftmax_kernel(float* __restrict__ out)
{
    int r = blockIdx.x;
    int t = r / BB, b = r % BB;
    const float4* row = reinterpret_cast<const float4*>(g_logits + (size_t)r * VOC);
    const int NV = VOC / 4;
    __shared__ float red[512];
    float mx = -1e30f;
    for (int v = threadIdx.x; v < NV; v += 512) {
        float4 x = row[v];
        mx = fmaxf(mx, fmaxf(fmaxf(x.x, x.y), fmaxf(x.z, x.w)));
    }
    red[threadIdx.x] = mx; __syncthreads();
    for (int s = 256; s > 0; s >>= 1) {
        if (threadIdx.x < s) red[threadIdx.x] = fmaxf(red[threadIdx.x], red[threadIdx.x + s]);
        __syncthreads();
    }
    mx = red[0]; __syncthreads();
    float sum = 0.f;
    for (int v = threadIdx.x; v < NV; v += 512) {
        float4 x = row[v];
        sum += expf(x.x - mx) + expf(x.y - mx) + expf(x.z - mx) + expf(x.w - mx);
    }
    red[threadIdx.x] = sum; __syncthreads();
    for (int s = 256; s > 0; s >>= 1) {
        if (threadIdx.x < s) red[threadIdx.x] += red[threadIdx.x + s];
        __syncthreads();
    }
    float lse = mx + logf(red[0]);
    float4* orow = reinterpret_cast<float4*>(out + ((size_t)b * TT + t) * VOC);
    for (int v = threadIdx.x; v < NV; v += 512) {
        float4 x = row[v];
        orow[v] = make_float4(x.x - lse, x.y - lse, x.z - lse, x.w - lse);
    }
}

// ==================== host ====================
static inline void tc(const bf16* A, int lda, const bf16* B, int ldb,
                      const float* bias, float* C, bf16* Cb, int ldc,
                      int Mtiles, int N, int K, int act)
{
    dim3 grid((N + 127) / 128, Mtiles);
    gemm_bf<<<grid, 256, SMEM_MM>>>(A, lda, B, ldb, bias, C, Cb, ldc, N, K, act);
}

static inline void conv(const float* in, bf16* out, int n)
{
    int n4 = n / 4;
    f2bf<<<(n4 + 255) / 256, 256>>>(in, out, n4);
}

extern "C" void kernel_launch(void* const* d_in, const int* in_sizes, int n_in,
                              void* d_out, int out_size)
{
    const float* image = (const float*)d_in[0];
    const int*   target = (const int*)d_in[1];
    const float* emb = (const float*)d_in[2];
    const float* Wa = (const float*)d_in[3];  const float* ba = (const float*)d_in[4];
    const float* Wb = (const float*)d_in[5];  const float* bb = (const float*)d_in[6];
    const float* Whi = (const float*)d_in[7]; const float* bhi = (const float*)d_in[8];
    const float* Wmi = (const float*)d_in[9]; const float* bmi = (const float*)d_in[10];
    const float* Wih = (const float*)d_in[11]; const float* bih = (const float*)d_in[12];
    const float* Whh = (const float*)d_in[13]; const float* bhh = (const float*)d_in[14];
    const float* Wv = (const float*)d_in[15];
    const float* Wg = (const float*)d_in[16];
    const float* wh = (const float*)d_in[17];
    const float* WH = (const float*)d_in[18];
    const float* Wx = (const float*)d_in[19];
    const float* Wh2 = (const float*)d_in[20];
    const float* Ws = (const float*)d_in[21];
    const float* Wc = (const float*)d_in[22]; const float* bc = (const float*)d_in[23];
    const float* Wfc = (const float*)d_in[24]; const float* bfc = (const float*)d_in[25];
    const float* Wp = (const float*)d_in[26]; const float* bp = (const float*)d_in[27];

    float* out = (float*)d_out;
    float* out_attn = out + (size_t)BB * TT * VOC;

    float *p_Vf, *p_zbase, *p_bcat, *p_vg, *p_m, *p_tm, *p_bsum, *p_xg, *p_xx;
    float *p_G1, *p_H, *p_s, *p_gH, *p_sWs, *p_out, *p_logits, *p_init;
    bf16 *pb_image, *pb_Wa, *pb_mean, *pb_Wcat, *pb_xcat, *pb_Wih, *pb_Wx, *pb_Whh;
    bf16 *pb_Wh2, *pb_WH, *pb_Wc, *pb_Wfc, *pb_Wp, *pb_Wg, *pb_Ws;
    bf16 *pb_hseq, *pb_a, *pb_ctxH, *pb_out, *pb_Vfb, *pb_H, *pb_s;
    cudaGetSymbolAddress((void**)&p_Vf, g_Vf);
    cudaGetSymbolAddress((void**)&p_zbase, g_zbase);
    cudaGetSymbolAddress((void**)&p_bcat, g_bcat);
    cudaGetSymbolAddress((void**)&p_init, g_init);
    cudaGetSymbolAddress((void**)&p_vg, g_vg);
    cudaGetSymbolAddress((void**)&p_m, g_m);
    cudaGetSymbolAddress((void**)&p_tm, g_tm);
    cudaGetSymbolAddress((void**)&p_bsum, g_bsum);
    cudaGetSymbolAddress((void**)&p_xg, g_xg);
    cudaGetSymbolAddress((void**)&p_xx, g_xx);
    cudaGetSymbolAddress((void**)&p_G1, g_G1);
    cudaGetSymbolAddress((void**)&p_H, g_H);
    cudaGetSymbolAddress((void**)&p_s, g_s);
    cudaGetSymbolAddress((void**)&p_gH, g_gH);
    cudaGetSymbolAddress((void**)&p_sWs, g_sWs);
    cudaGetSymbolAddress((void**)&p_out, g_out);
    cudaGetSymbolAddress((void**)&p_logits, g_logits);
    cudaGetSymbolAddress((void**)&pb_image, g_image_bf);
    cudaGetSymbolAddress((void**)&pb_Wa, g_Wa_bf);
    cudaGetSymbolAddress((void**)&pb_mean, g_mean_bf);
    cudaGetSymbolAddress((void**)&pb_Wcat, g_Wcat_bf);
    cudaGetSymbolAddress((void**)&pb_xcat, g_xcat_bf);
    cudaGetSymbolAddress((void**)&pb_Wih, g_Wih_bf);
    cudaGetSymbolAddress((void**)&pb_Wx, g_Wx_bf);
    cudaGetSymbolAddress((void**)&pb_Whh, g_Whh_bf);
    cudaGetSymbolAddress((void**)&pb_Wh2, g_Wh2_bf);
    cudaGetSymbolAddress((void**)&pb_WH, g_WH_bf);
    cudaGetSymbolAddress((void**)&pb_Wc, g_Wc_bf);
    cudaGetSymbolAddress((void**)&pb_Wfc, g_Wfc_bf);
    cudaGetSymbolAddress((void**)&pb_Wp, g_Wp_bf);
    cudaGetSymbolAddress((void**)&pb_Wg, g_Wg_bf);
    cudaGetSymbolAddress((void**)&pb_Ws, g_Ws_bf);
    cudaGetSymbolAddress((void**)&pb_hseq, g_hseq_bf);
    cudaGetSymbolAddress((void**)&pb_a, g_a_bf);
    cudaGetSymbolAddress((void**)&pb_ctxH, g_ctxH_bf);
    cudaGetSymbolAddress((void**)&pb_out, g_out_bf);
    cudaGetSymbolAddress((void**)&pb_Vfb, g_Vfb);
    cudaGetSymbolAddress((void**)&pb_H, g_H_bf);
    cudaGetSymbolAddress((void**)&pb_s, g_s_bf);

    static int attr_set = 0;
    if (!attr_set) {
        cudaFuncSetAttribute(lstm_persistent, cudaFuncAttributeMaxDynamicSharedMemorySize, LSTM_SMEM);
        attr_set = 1;
    }

    // ---- conversions ----
    conv(image, pb_image, BB * NN * CC);
    conv(Wa, pb_Wa, DD * CC);
    conv(Wih, pb_Wih, 4 * DD * (DD + EE));
    conv(Wx, pb_Wx, DD * (DD + EE));
    conv(Whh, pb_Whh, 4 * DD * DD);
    conv(Wh2, pb_Wh2, DD * DD);
    conv(WH, pb_WH, DD * DD);
    conv(Wc, pb_Wc, DD * DD);
    conv(Wfc, pb_Wfc, DD * DD);
    conv(Wp, pb_Wp, VOC * DD);
    conv(Wg, pb_Wg, NN * DD);
    conv(Ws, pb_Ws, NN * DD);
    bias_sum<<<(4 * DD + 255) / 256, 256>>>(bih, bhh);

    // ---- precompute ----
    mean_kernel<<<(BB * CC + 255) / 256, 256>>>(image, pb_mean);
    tc(pb_image, CC, pb_Wa, CC, ba, p_Vf, pb_Vfb, DD, BB * NN / 128, DD, CC, 1);
    cat_w3<<<(3 * DD * CC + 255) / 256, 256>>>(Wb, Whi, Wmi, pb_Wcat);
    cat_bias3<<<(3 * DD + 255) / 256, 256>>>(bb, bhi, bmi, p_bcat);
    tc(pb_mean, CC, pb_Wcat, CC, p_bcat, p_init, nullptr, 3 * DD, 1, 3 * DD, CC, 1);
    split_init<<<(BB * DD + 255) / 256, 256>>>(p_vg, pb_hseq, p_m);
    {
        dim3 grid(1, 1, BB);
        gemm_nt<64, 64, 16, 4, 4><<<grid, 256>>>(p_Vf, DD, Wv, DD, p_zbase, NN,
                                                 NN, NN, DD,
                                                 (long long)NN * DD, 0, (long long)NN * NN);
    }
    xcat_build<<<(RR * (DD + EE) + 255) / 256, 256>>>(target, emb);
    tc(pb_xcat, DD + EE, pb_Wih, DD + EE, p_bsum, p_xg, nullptr, 4 * DD, RR / 128, 4 * DD, DD + EE, 0);
    tc(pb_xcat, DD + EE, pb_Wx, DD + EE, nullptr, p_xx, nullptr, DD, RR / 128, DD, DD + EE, 0);

    // ---- sequential recurrence: ONE persistent kernel ----
    bar_reset<<<1, 32>>>();
    lstm_persistent<<<16, 256, LSTM_SMEM>>>(pb_Whh, p_xg, p_m, pb_hseq, p_tm);

    // ---- batched epilogue over RR rows ----
    const bf16* Hp = pb_hseq;
    const bf16* Hc = pb_hseq + (size_t)BB * DD;
    tc(Hp, DD, pb_Wh2, DD, nullptr, p_G1, nullptr, DD, RR / 128, DD, DD, 0);
    tc(Hc, DD, pb_WH, DD, nullptr, p_H, pb_H, DD, RR / 128, DD, DD, 1);
    gate_a<<<(RR * DD + 255) / 256, 256>>>();
    tc(pb_a, DD, pb_Wc, DD, bc, p_s, pb_s, DD, RR / 128, DD, DD, 1);
    tc(pb_H, DD, pb_Wg, DD, nullptr, p_gH, nullptr, NN, RR / 128, NN, DD, 0);
    tc(pb_s, DD, pb_Ws, DD, nullptr, p_sWs, nullptr, NN, RR / 128, NN, DD, 0);
    attn_batched<<<RR, 256>>>(wh, out_attn);
    tc(pb_ctxH, DD, pb_Wfc, DD, bfc, p_out, pb_out, DD, RR / 128, DD, DD, 2);

    // ---- logits + log_softmax ----
    tc(pb_out, DD, pb_Wp, DD, bp, p_logits, nullptr, VOC, RR / 128, VOC, DD, 0);
    logsoftmax_kernel<<<RR, 512>>>(out);
}

// round 9
// speedup vs baseline: 1.1749x; 1.1749x over previous
#include <cuda_runtime.h>
#include <cuda_bf16.h>
#include <math.h>
#include <stdint.h>

#define BB 128
#define NN 49
#define CC 2048
#define DD 512
#define EE 512
#define VOC 10000
#define TT 20
#define RR (TT * BB)

typedef __nv_bfloat16 bf16;
typedef __nv_bfloat162 bf162;

// ---------------- fp32 scratch ----------------
__device__ float g_Vf[BB * NN * DD];
__device__ float g_zbase[BB * NN * NN];
__device__ float g_bcat[3 * DD];
__device__ float g_init[BB * 3 * DD];
__device__ float g_vg[BB * DD];
__device__ float g_m[BB * DD];
__device__ float g_tm[RR * DD];
__device__ float g_bsum[4 * DD];
__device__ float g_xg[RR * 4 * DD];
__device__ float g_xx[RR * DD];
__device__ float g_gates[BB * 4 * DD];
__device__ float g_H[RR * DD];
__device__ float g_s[RR * DD];
__device__ float g_gH[RR * NN];
__device__ float g_sWs[RR * NN];
__device__ float g_out[RR * DD];
__device__ float g_logits[(size_t)RR * VOC];

// ---------------- bf16 scratch ----------------
__device__ __align__(16) bf16 g_image_bf[BB * NN * CC];
__device__ __align__(16) bf16 g_Wa_bf[DD * CC];
__device__ __align__(16) bf16 g_mean_bf[BB * CC];
__device__ __align__(16) bf16 g_Wcat_bf[3 * DD * CC];
__device__ __align__(16) bf16 g_xcat_bf[RR * (DD + EE)];
__device__ __align__(16) bf16 g_Wih_bf[4 * DD * (DD + EE)];
__device__ __align__(16) bf16 g_Wx_bf[DD * (DD + EE)];
__device__ __align__(16) bf16 g_Whh_bf[4 * DD * DD];
__device__ __align__(16) bf16 g_Wh2_bf[DD * DD];
__device__ __align__(16) bf16 g_WH_bf[DD * DD];
__device__ __align__(16) bf16 g_Wc_bf[DD * DD];
__device__ __align__(16) bf16 g_Wfc_bf[DD * DD];
__device__ __align__(16) bf16 g_Wp_bf[VOC * DD];
__device__ __align__(16) bf16 g_Wg_bf[NN * DD];
__device__ __align__(16) bf16 g_Ws_bf[NN * DD];
__device__ __align__(16) bf16 g_hseq_bf[(TT + 1) * BB * DD];
__device__ __align__(16) bf16 g_a_bf[RR * DD];
__device__ __align__(16) bf16 g_ctxH_bf[RR * DD];
__device__ __align__(16) bf16 g_out_bf[RR * DD];
__device__ __align__(16) bf16 g_Vfb[BB * NN * DD];
__device__ __align__(16) bf16 g_H_bf[RR * DD];
__device__ __align__(16) bf16 g_s_bf[RR * DD];

__device__ __forceinline__ float sigmoidf_(float x) { return 1.f / (1.f + expf(-x)); }

__device__ __forceinline__ uint32_t smem_u32(const void* p) {
    uint32_t a;
    asm("{ .reg .u64 t; cvta.to.shared.u64 t, %1; cvt.u32.u64 %0, t; }" : "=r"(a) : "l"(p));
    return a;
}

__device__ __forceinline__ void cp_async16(uint32_t dst, const void* src, bool pred) {
    int sz = pred ? 16 : 0;
    asm volatile("cp.async.cg.shared.global [%0], [%1], 16, %2;"
                 :: "r"(dst), "l"(src), "r"(sz) : "memory");
}
#define CP_COMMIT() asm volatile("cp.async.commit_group;" ::: "memory")
#define CP_WAIT1()  asm volatile("cp.async.wait_group 1;" ::: "memory")

__device__ __forceinline__ void mma_bf16(float* c, const uint32_t* a, uint32_t b0, uint32_t b1)
{
    asm volatile(
        "mma.sync.aligned.m16n8k16.row.col.f32.bf16.bf16.f32 "
        "{%0,%1,%2,%3}, {%4,%5,%6,%7}, {%8,%9}, {%0,%1,%2,%3};"
        : "+f"(c[0]), "+f"(c[1]), "+f"(c[2]), "+f"(c[3])
        : "r"(a[0]), "r"(a[1]), "r"(a[2]), "r"(a[3]), "r"(b0), "r"(b1));
}

#define ASTR 40
#define ABUF (128 * ASTR)
#define SMEM_MM (4 * ABUF * 2)

// ==================== generic bf16 HMMA GEMM (BN=128) ====================
// act: 0 none, 1 relu, 2 tanh, 3: Cb = bf16( sigmoid(aux1+v)*aux2 ) only.
__global__ void __launch_bounds__(256, 2) gemm_bf(
    const bf16* __restrict__ A, int lda,
    const bf16* __restrict__ B, int ldb,
    const float* __restrict__ bias,
    float* __restrict__ C, bf16* __restrict__ Cb, int ldc,
    int N, int K, int act,
    const float* __restrict__ aux1, const float* __restrict__ aux2)
{
    extern __shared__ bf16 sm[];
    bf16* sA[2] = { sm, sm + ABUF };
    bf16* sB[2] = { sm + 2 * ABUF, sm + 3 * ABUF };
    const uint32_t sA_u[2] = { smem_u32(sA[0]), smem_u32(sA[1]) };
    const uint32_t sB_u[2] = { smem_u32(sB[0]), smem_u32(sB[1]) };

    const int tid = threadIdx.x;
    const int wid = tid >> 5, lane = tid & 31;
    const int g = lane >> 2, tg = lane & 3;
    const int wm = (wid & 3) * 32;
    const int wn = (wid >> 2) * 64;
    const int m0 = blockIdx.y * 128;
    const int n0 = blockIdx.x * 128;

    A += (size_t)m0 * lda;

    float acc[2][8][4];
#pragma unroll
    for (int mi = 0; mi < 2; mi++)
#pragma unroll
        for (int ni = 0; ni < 8; ni++)
#pragma unroll
            for (int q = 0; q < 4; q++) acc[mi][ni][q] = 0.f;

    const int KI = K >> 5;
    const int r_ld = tid >> 2;
    const int c16 = tid & 3;

    {
#pragma unroll
        for (int j = 0; j < 2; j++) {
            int row = r_ld + j * 64;
            cp_async16(sA_u[0] + (row * ASTR + c16 * 8) * 2,
                       A + (size_t)row * lda + c16 * 8, true);
        }
#pragma unroll
        for (int j = 0; j < 2; j++) {
            int row = r_ld + j * 64;
            int gn = n0 + row;
            bool ok = gn < N;
            int gs = ok ? gn : (N - 1);
            cp_async16(sB_u[0] + (row * ASTR + c16 * 8) * 2,
                       B + (size_t)gs * ldb + c16 * 8, ok);
        }
        CP_COMMIT();
    }

    for (int i = 0; i < KI; i++) {
        const int cur = i & 1;
        if (i + 1 < KI) {
            const int nxt = cur ^ 1;
            const int k0 = (i + 1) << 5;
#pragma unroll
            for (int j = 0; j < 2; j++) {
                int row = r_ld + j * 64;
                cp_async16(sA_u[nxt] + (row * ASTR + c16 * 8) * 2,
                           A + (size_t)row * lda + k0 + c16 * 8, true);
            }
#pragma unroll
            for (int j = 0; j < 2; j++) {
                int row = r_ld + j * 64;
                int gn = n0 + row;
                bool ok = gn < N;
                int gs = ok ? gn : (N - 1);
                cp_async16(sB_u[nxt] + (row * ASTR + c16 * 8) * 2,
                           B + (size_t)gs * ldb + k0 + c16 * 8, ok);
            }
        }
        CP_COMMIT();
        CP_WAIT1();
        __syncthreads();

        const uint32_t* As_ = reinterpret_cast<const uint32_t*>(sA[cur]);
        const uint32_t* Bs_ = reinterpret_cast<const uint32_t*>(sB[cur]);
#pragma unroll
        for (int kk = 0; kk < 2; kk++) {
            const int kw = kk * 8;
            uint32_t a[2][4];
#pragma unroll
            for (int mi = 0; mi < 2; mi++) {
                int r = wm + mi * 16 + g;
                a[mi][0] = As_[r * 20 + kw + tg];
                a[mi][1] = As_[(r + 8) * 20 + kw + tg];
                a[mi][2] = As_[r * 20 + kw + 4 + tg];
                a[mi][3] = As_[(r + 8) * 20 + kw + 4 + tg];
            }
#pragma unroll
            for (int ni = 0; ni < 8; ni++) {
                int rn = wn + ni * 8 + g;
                uint32_t b0 = Bs_[rn * 20 + kw + tg];
                uint32_t b1 = Bs_[rn * 20 + kw + 4 + tg];
                mma_bf16(acc[0][ni], a[0], b0, b1);
                mma_bf16(acc[1][ni], a[1], b0, b1);
            }
        }
        __syncthreads();
    }

#pragma unroll
    for (int mi = 0; mi < 2; mi++) {
#pragma unroll
        for (int ni = 0; ni < 8; ni++) {
            int gr = m0 + wm + mi * 16 + g;
            int gc = n0 + wn + ni * 8 + 2 * tg;
#pragma unroll
            for (int q = 0; q < 4; q++) {
                int r = gr + (q >> 1) * 8;
                int c = gc + (q & 1);
                if (c < N) {
                    float v = acc[mi][ni][q];
                    size_t off = (size_t)r * ldc + c;
                    if (act == 3) {
                        float av = sigmoidf_(aux1[off] + v) * aux2[off];
                        Cb[off] = __float2bfloat16_rn(av);
                    } else {
                        if (bias) v += bias[c];
                        if (act == 1) v = fmaxf(v, 0.f);
                        else if (act == 2) v = tanhf(v);
                        C[off] = v;
                        if (Cb) Cb[off] = __float2bfloat16_rn(v);
                    }
                }
            }
        }
    }
}

// ==================== BN=64 bf16 HMMA GEMM ====================
#define BBUF64 (64 * ASTR)
#define SMEM_MM64 ((2 * ABUF + 2 * BBUF64) * 2)

__global__ void __launch_bounds__(256, 2) gemm_bf64(
    const bf16* __restrict__ A, int lda,
    const bf16* __restrict__ B, int ldb,
    const float* __restrict__ bias,
    float* __restrict__ C, bf16* __restrict__ Cb, int ldc,
    int N, int K, int act)
{
    extern __shared__ bf16 sm[];
    bf16* sA[2] = { sm, sm + ABUF };
    bf16* sB[2] = { sm + 2 * ABUF, sm + 2 * ABUF + BBUF64 };
    const uint32_t sA_u[2] = { smem_u32(sA[0]), smem_u32(sA[1]) };
    const uint32_t sB_u[2] = { smem_u32(sB[0]), smem_u32(sB[1]) };

    const int tid = threadIdx.x;
    const int wid = tid >> 5, lane = tid & 31;
    const int g = lane >> 2, tg = lane & 3;
    const int wm = (wid & 3) * 32;
    const int wn = (wid >> 2) * 32;
    const int m0 = blockIdx.y * 128;
    const int n0 = blockIdx.x * 64;

    A += (size_t)m0 * lda;

    float acc[2][4][4];
#pragma unroll
    for (int mi = 0; mi < 2; mi++)
#pragma unroll
        for (int ni = 0; ni < 4; ni++)
#pragma unroll
            for (int q = 0; q < 4; q++) acc[mi][ni][q] = 0.f;

    const int KI = K >> 5;
    const int r_ld = tid >> 2;
    const int c16 = tid & 3;

    {
#pragma unroll
        for (int j = 0; j < 2; j++) {
            int row = r_ld + j * 64;
            cp_async16(sA_u[0] + (row * ASTR + c16 * 8) * 2,
                       A + (size_t)row * lda + c16 * 8, true);
        }
        {
            int row = r_ld;
            int gn = n0 + row;
            bool ok = (row < 64) && (gn < N);
            int gs = (gn < N) ? gn : (N - 1);
            if (row < 64)
                cp_async16(sB_u[0] + (row * ASTR + c16 * 8) * 2,
                           B + (size_t)gs * ldb + c16 * 8, ok);
        }
        CP_COMMIT();
    }

    for (int i = 0; i < KI; i++) {
        const int cur = i & 1;
        if (i + 1 < KI) {
            const int nxt = cur ^ 1;
            const int k0 = (i + 1) << 5;
#pragma unroll
            for (int j = 0; j < 2; j++) {
                int row = r_ld + j * 64;
                cp_async16(sA_u[nxt] + (row * ASTR + c16 * 8) * 2,
                           A + (size_t)row * lda + k0 + c16 * 8, true);
            }
            {
                int row = r_ld;
                int gn = n0 + row;
                bool ok = (row < 64) && (gn < N);
                int gs = (gn < N) ? gn : (N - 1);
                if (row < 64)
                    cp_async16(sB_u[nxt] + (row * ASTR + c16 * 8) * 2,
                               B + (size_t)gs * ldb + k0 + c16 * 8, ok);
            }
        }
        CP_COMMIT();
        CP_WAIT1();
        __syncthreads();

        const uint32_t* As_ = reinterpret_cast<const uint32_t*>(sA[cur]);
        const uint32_t* Bs_ = reinterpret_cast<const uint32_t*>(sB[cur]);
#pragma unroll
        for (int kk = 0; kk < 2; kk++) {
            const int kw = kk * 8;
            uint32_t a[2][4];
#pragma unroll
            for (int mi = 0; mi < 2; mi++) {
                int r = wm + mi * 16 + g;
                a[mi][0] = As_[r * 20 + kw + tg];
                a[mi][1] = As_[(r + 8) * 20 + kw + tg];
                a[mi][2] = As_[r * 20 + kw + 4 + tg];
                a[mi][3] = As_[(r + 8) * 20 + kw + 4 + tg];
            }
#pragma unroll
            for (int ni = 0; ni < 4; ni++) {
                int rn = wn + ni * 8 + g;
                uint32_t b0 = Bs_[rn * 20 + kw + tg];
                uint32_t b1 = Bs_[rn * 20 + kw + 4 + tg];
                mma_bf16(acc[0][ni], a[0], b0, b1);
                mma_bf16(acc[1][ni], a[1], b0, b1);
            }
        }
        __syncthreads();
    }

#pragma unroll
    for (int mi = 0; mi < 2; mi++) {
#pragma unroll
        for (int ni = 0; ni < 4; ni++) {
            int gr = m0 + wm + mi * 16 + g;
            int gc = n0 + wn + ni * 8 + 2 * tg;
#pragma unroll
            for (int q = 0; q < 4; q++) {
                int r = gr + (q >> 1) * 8;
                int c = gc + (q & 1);
                if (c < N) {
                    float v = acc[mi][ni][q];
                    if (bias) v += bias[c];
                    if (act == 1) v = fmaxf(v, 0.f);
                    else if (act == 2) v = tanhf(v);
                    C[(size_t)r * ldc + c] = v;
                    if (Cb) Cb[(size_t)r * ldc + c] = __float2bfloat16_rn(v);
                }
            }
        }
    }
}

// ==================== SIMT GEMM (zbase only) ====================
template <int BM, int BN, int BK, int TM, int TN>
__global__ void gemm_nt(const float* __restrict__ A, int lda,
                        const float* __restrict__ Bm, int ldb,
                        float* __restrict__ C, int ldc,
                        int M, int N, int K,
                        long long sA, long long sB, long long sC)
{
    constexpr int THREADS = (BM / TM) * (BN / TN);
    __shared__ float As[BK][BM + 4];
    __shared__ float Bs[BK][BN + 4];

    A += (long long)blockIdx.z * sA;
    Bm += (long long)blockIdx.z * sB;
    C += (long long)blockIdx.z * sC;

    const int tid = threadIdx.x;
    const int bm0 = blockIdx.y * BM;
    const int bn0 = blockIdx.x * BN;
    const int tm = (tid / (BN / TN)) * TM;
    const int tn = (tid % (BN / TN)) * TN;

    float acc[TM][TN];
#pragma unroll
    for (int i = 0; i < TM; i++)
#pragma unroll
        for (int j = 0; j < TN; j++) acc[i][j] = 0.f;

    for (int k0 = 0; k0 < K; k0 += BK) {
#pragma unroll
        for (int i = tid; i < BM * (BK / 4); i += THREADS) {
            int row = i / (BK / 4);
            int kc = i % (BK / 4);
            int gm = bm0 + row;
            int gk = k0 + kc * 4;
            float4 v = make_float4(0.f, 0.f, 0.f, 0.f);
            if (gm < M) v = *reinterpret_cast<const float4*>(A + (size_t)gm * lda + gk);
            As[kc * 4 + 0][row] = v.x; As[kc * 4 + 1][row] = v.y;
            As[kc * 4 + 2][row] = v.z; As[kc * 4 + 3][row] = v.w;
        }
#pragma unroll
        for (int i = tid; i < BN * (BK / 4); i += THREADS) {
            int row = i / (BK / 4);
            int kc = i % (BK / 4);
            int gn = bn0 + row;
            int gk = k0 + kc * 4;
            float4 v = make_float4(0.f, 0.f, 0.f, 0.f);
            if (gn < N) v = *reinterpret_cast<const float4*>(Bm + (size_t)gn * ldb + gk);
            Bs[kc * 4 + 0][row] = v.x; Bs[kc * 4 + 1][row] = v.y;
            Bs[kc * 4 + 2][row] = v.z; Bs[kc * 4 + 3][row] = v.w;
        }
        __syncthreads();
#pragma unroll
        for (int k = 0; k < BK; k++) {
            float ra[TM], rb[TN];
#pragma unroll
            for (int i = 0; i < TM; i++) ra[i] = As[k][tm + i];
#pragma unroll
            for (int j = 0; j < TN; j++) rb[j] = Bs[k][tn + j];
#pragma unroll
            for (int i = 0; i < TM; i++)
#pragma unroll
                for (int j = 0; j < TN; j++) acc[i][j] += ra[i] * rb[j];
        }
        __syncthreads();
    }

#pragma unroll
    for (int i = 0; i < TM; i++) {
        int gm = bm0 + tm + i;
        if (gm >= M) continue;
#pragma unroll
        for (int j = 0; j < TN; j++) {
            int gn = bn0 + tn + j;
            if (gn >= N) continue;
            C[(size_t)gm * ldc + gn] = acc[i][j];
        }
    }
}

// ==================== small kernels ====================
#define NSEG 12
struct ConvSegs {
    const float* src[NSEG];
    bf16* dst[NSEG];
    int n4[NSEG];
};

__global__ void f2bf_multi(ConvSegs segs, int total4)
{
    int i = blockIdx.x * blockDim.x + threadIdx.x;
    if (i >= total4) return;
    int idx = i;
#pragma unroll
    for (int s = 0; s < NSEG; s++) {
        if (idx < segs.n4[s]) {
            float4 v = reinterpret_cast<const float4*>(segs.src[s])[idx];
            bf162* o = reinterpret_cast<bf162*>(segs.dst[s]) + idx * 2;
            o[0] = __floats2bfloat162_rn(v.x, v.y);
            o[1] = __floats2bfloat162_rn(v.z, v.w);
            return;
        }
        idx -= segs.n4[s];
    }
}

__global__ void mean_kernel(const float* __restrict__ x, bf16* __restrict__ mean_bf)
{
    int idx = blockIdx.x * blockDim.x + threadIdx.x;
    if (idx >= BB * CC) return;
    int b = idx / CC, c = idx % CC;
    float acc = 0.f;
    const float* p = x + (size_t)b * NN * CC + c;
#pragma unroll 7
    for (int n = 0; n < NN; n++) acc += p[(size_t)n * CC];
    mean_bf[idx] = __float2bfloat16_rn(acc * (1.f / (float)NN));
}

__global__ void cat_w3(const float* __restrict__ Wb, const float* __restrict__ Whi,
                       const float* __restrict__ Wmi, bf16* __restrict__ Wcat)
{
    int idx = blockIdx.x * blockDim.x + threadIdx.x;
    if (idx >= 3 * DD * CC) return;
    int r = idx / CC;
    const float* src = (r < DD) ? Wb : (r < 2 * DD) ? Whi : Wmi;
    int rr = (r < DD) ? r : (r < 2 * DD) ? r - DD : r - 2 * DD;
    Wcat[idx] = __float2bfloat16_rn(src[(size_t)rr * CC + (idx % CC)]);
}

__global__ void cat_bias3(const float* __restrict__ bb, const float* __restrict__ bhi,
                          const float* __restrict__ bmi, float* __restrict__ bcat,
                          const float* __restrict__ bih, const float* __restrict__ bhh,
                          float* __restrict__ bsum)
{
    int i = blockIdx.x * blockDim.x + threadIdx.x;
    if (i < 3 * DD)
        bcat[i] = (i < DD) ? bb[i] : (i < 2 * DD) ? bhi[i - DD] : bmi[i - 2 * DD];
    if (i < 4 * DD)
        bsum[i] = bih[i] + bhh[i];
}

__global__ void split_init(float* __restrict__ vg, bf16* __restrict__ h0,
                           float* __restrict__ m0)
{
    int idx = blockIdx.x * blockDim.x + threadIdx.x;
    if (idx >= BB * DD) return;
    int b = idx >> 9, d = idx & (DD - 1);
    const float* row = g_init + (size_t)b * (3 * DD);
    vg[idx] = row[d];
    h0[idx] = __float2bfloat16_rn(row[DD + d]);
    m0[idx] = row[2 * DD + d];
}

__global__ void xcat_build(const int* __restrict__ target, const float* __restrict__ emb)
{
    int idx = blockIdx.x * blockDim.x + threadIdx.x;
    if (idx >= RR * (DD + EE)) return;
    int c = idx & 1023;
    int r = idx >> 10;
    int b = r % BB, t = r / BB;
    float v;
    if (c < DD) {
        v = g_vg[(size_t)b * DD + c];
    } else {
        v = 0.f;
        if (t > 0) v = emb[(size_t)target[b * TT + (t - 1)] * EE + (c - DD)];
    }
    g_xcat_bf[idx] = __float2bfloat16_rn(v);
}

__global__ void lstm_elem(const float* __restrict__ xg_t,
                          float* __restrict__ m,
                          bf16* __restrict__ h_out,
                          float* __restrict__ tm_out)
{
    int idx = blockIdx.x * blockDim.x + threadIdx.x;
    if (idx >= BB * DD) return;
    int b = idx >> 9, d = idx & (DD - 1);
    const float* gr = g_gates + (size_t)b * (4 * DD);
    const float* xr = xg_t + (size_t)b * (4 * DD);
    float gi = gr[d] + xr[d];
    float gf = gr[DD + d] + xr[DD + d];
    float gg = gr[2 * DD + d] + xr[2 * DD + d];
    float go = gr[3 * DD + d] + xr[3 * DD + d];
    float m2 = sigmoidf_(gf) * m[idx] + sigmoidf_(gi) * tanhf(gg);
    float tm2 = tanhf(m2);
    m[idx] = m2;
    h_out[idx] = __float2bfloat16_rn(sigmoidf_(go) * tm2);
    tm_out[idx] = tm2;
}

__global__ void attn_batched(const float* __restrict__ wh, float* __restrict__ out_attn)
{
    int r = blockIdx.x;
    int t = r / BB, b = r % BB;
    int tid = threadIdx.x;
    __shared__ float gHs[NN], whs[NN], zs[NN + 1], alphas[NN + 1];
    if (tid < NN) { gHs[tid] = g_gH[(size_t)r * NN + tid]; whs[tid] = wh[tid]; }
    __syncthreads();

    if (tid < NN) {
        const float* zb = g_zbase + ((size_t)b * NN + tid) * NN;
        float acc = 0.f;
        for (int k = 0; k < NN; k++) acc += tanhf(zb[k] + gHs[k]) * whs[k];
        zs[tid] = acc;
    } else if (tid == NN) {
        const float* sw = g_sWs + (size_t)r * NN;
        float acc = 0.f;
        for (int k = 0; k < NN; k++) acc += tanhf(sw[k] + gHs[k]) * whs[k];
        zs[NN] = acc;
    }
    __syncthreads();

    if (tid == 0) {
        float mx = -1e30f;
        for (int i = 0; i <= NN; i++) mx = fmaxf(mx, zs[i]);
        float sum = 0.f;
        for (int i = 0; i <= NN; i++) { float e = expf(zs[i] - mx); alphas[i] = e; sum += e; }
        float inv = 1.f / sum;
        for (int i = 0; i <= NN; i++) alphas[i] *= inv;
    }
    __syncthreads();

    if (tid < NN) out_attn[((size_t)b * TT + t) * NN + tid] = alphas[tid];

    {
        int d = tid * 2;
        float aN = alphas[NN];
        float cx = aN * g_s[(size_t)r * DD + d];
        float cy = aN * g_s[(size_t)r * DD + d + 1];
        const bf162* vf = reinterpret_cast<const bf162*>(g_Vfb + (size_t)b * NN * DD + d);
#pragma unroll 7
        for (int n = 0; n < NN; n++) {
            float2 v = __bfloat1622float2(vf[n * (DD / 2)]);
            cx += alphas[n] * v.x;
            cy += alphas[n] * v.y;
        }
        cx += g_H[(size_t)r * DD + d];
        cy += g_H[(size_t)r * DD + d + 1];
        reinterpret_cast<bf162*>(g_ctxH_bf + (size_t)r * DD + d)[0] =
            __floats2bfloat162_rn(cx, cy);
    }
}

__global__ void logsoftmax_kernel(float* __restrict__ out)
{
    int r = blockIdx.x;
    int t = r / BB, b = r % BB;
    const float4* row = reinterpret_cast<const float4*>(g_logits + (size_t)r * VOC);
    const int NV = VOC / 4;
    __shared__ float red[512];
    float mx = -1e30f;
    for (int v = threadIdx.x; v < NV; v += 512) {
        float4 x = row[v];
        mx = fmaxf(mx, fmaxf(fmaxf(x.x, x.y), fmaxf(x.z, x.w)));
    }
    red[threadIdx.x] = mx; __syncthreads();
    for (int s = 256; s > 0; s >>= 1) {
        if (threadIdx.x < s) red[threadIdx.x] = fmaxf(red[threadIdx.x], red[threadIdx.x + s]);
        __syncthreads();
    }
    mx = red[0]; __syncthreads();
    float sum = 0.f;
    for (int v = threadIdx.x; v < NV; v += 512) {
        float4 x = row[v];
        sum += expf(x.x - mx) + expf(x.y - mx) + expf(x.z - mx) + expf(x.w - mx);
    }
    red[threadIdx.x] = sum; __syncthreads();
    for (int s = 256; s > 0; s >>= 1) {
        if (threadIdx.x < s) red[threadIdx.x] += red[threadIdx.x + s];
        __syncthreads();
    }
    float lse = mx + logf(red[0]);
    float4* orow = reinterpret_cast<float4*>(out + ((size_t)b * TT + t) * VOC);
    for (int v = threadIdx.x; v < NV; v += 512) {
        float4 x = row[v];
        orow[v] = make_float4(x.x - lse, x.y - lse, x.z - lse, x.w - lse);
    }
}

// ==================== host ====================
static inline void tc(const bf16* A, int lda, const bf16* B, int ldb,
                      const float* bias, float* C, bf16* Cb, int ldc,
                      int Mtiles, int N, int K, int act,
                      const float* aux1 = nullptr, const float* aux2 = nullptr)
{
    dim3 grid((N + 127) / 128, Mtiles);
    gemm_bf<<<grid, 256, SMEM_MM>>>(A, lda, B, ldb, bias, C, Cb, ldc, N, K, act, aux1, aux2);
}

static inline void tc64(const bf16* A, int lda, const bf16* B, int ldb,
                        const float* bias, float* C, bf16* Cb, int ldc,
                        int Mtiles, int N, int K, int act)
{
    dim3 grid((N + 63) / 64, Mtiles);
    gemm_bf64<<<grid, 256, SMEM_MM64>>>(A, lda, B, ldb, bias, C, Cb, ldc, N, K, act);
}

extern "C" void kernel_launch(void* const* d_in, const int* in_sizes, int n_in,
                              void* d_out, int out_size)
{
    const float* image = (const float*)d_in[0];
    const int*   target = (const int*)d_in[1];
    const float* emb = (const float*)d_in[2];
    const float* Wa = (const float*)d_in[3];  const float* ba = (const float*)d_in[4];
    const float* Wb = (const float*)d_in[5];  const float* bb = (const float*)d_in[6];
    const float* Whi = (const float*)d_in[7]; const float* bhi = (const float*)d_in[8];
    const float* Wmi = (const float*)d_in[9]; const float* bmi = (const float*)d_in[10];
    const float* Wih = (const float*)d_in[11]; const float* bih = (const float*)d_in[12];
    const float* Whh = (const float*)d_in[13]; const float* bhh = (const float*)d_in[14];
    const float* Wv = (const float*)d_in[15];
    const float* Wg = (const float*)d_in[16];
    const float* wh = (const float*)d_in[17];
    const float* WH = (const float*)d_in[18];
    const float* Wx = (const float*)d_in[19];
    const float* Wh2 = (const float*)d_in[20];
    const float* Ws = (const float*)d_in[21];
    const float* Wc = (const float*)d_in[22]; const float* bc = (const float*)d_in[23];
    const float* Wfc = (const float*)d_in[24]; const float* bfc = (const float*)d_in[25];
    const float* Wp = (const float*)d_in[26]; const float* bp = (const float*)d_in[27];

    float* out = (float*)d_out;
    float* out_attn = out + (size_t)BB * TT * VOC;

    float *p_Vf, *p_zbase, *p_bcat, *p_vg, *p_m, *p_tm, *p_bsum, *p_xg, *p_xx, *p_gates;
    float *p_H, *p_s, *p_gH, *p_sWs, *p_out, *p_logits, *p_init;
    bf16 *pb_image, *pb_Wa, *pb_mean, *pb_Wcat, *pb_xcat, *pb_Wih, *pb_Wx, *pb_Whh;
    bf16 *pb_Wh2, *pb_WH, *pb_Wc, *pb_Wfc, *pb_Wp, *pb_Wg, *pb_Ws;
    bf16 *pb_hseq, *pb_a, *pb_ctxH, *pb_out, *pb_Vfb, *pb_H, *pb_s;
    cudaGetSymbolAddress((void**)&p_Vf, g_Vf);
    cudaGetSymbolAddress((void**)&p_zbase, g_zbase);
    cudaGetSymbolAddress((void**)&p_bcat, g_bcat);
    cudaGetSymbolAddress((void**)&p_init, g_init);
    cudaGetSymbolAddress((void**)&p_vg, g_vg);
    cudaGetSymbolAddress((void**)&p_m, g_m);
    cudaGetSymbolAddress((void**)&p_tm, g_tm);
    cudaGetSymbolAddress((void**)&p_bsum, g_bsum);
    cudaGetSymbolAddress((void**)&p_xg, g_xg);
    cudaGetSymbolAddress((void**)&p_xx, g_xx);
    cudaGetSymbolAddress((void**)&p_gates, g_gates);
    cudaGetSymbolAddress((void**)&p_H, g_H);
    cudaGetSymbolAddress((void**)&p_s, g_s);
    cudaGetSymbolAddress((void**)&p_gH, g_gH);
    cudaGetSymbolAddress((void**)&p_sWs, g_sWs);
    cudaGetSymbolAddress((void**)&p_out, g_out);
    cudaGetSymbolAddress((void**)&p_logits, g_logits);
    cudaGetSymbolAddress((void**)&pb_image, g_image_bf);
    cudaGetSymbolAddress((void**)&pb_Wa, g_Wa_bf);
    cudaGetSymbolAddress((void**)&pb_mean, g_mean_bf);
    cudaGetSymbolAddress((void**)&pb_Wcat, g_Wcat_bf);
    cudaGetSymbolAddress((void**)&pb_xcat, g_xcat_bf);
    cudaGetSymbolAddress((void**)&pb_Wih, g_Wih_bf);
    cudaGetSymbolAddress((void**)&pb_Wx, g_Wx_bf);
    cudaGetSymbolAddress((void**)&pb_Whh, g_Whh_bf);
    cudaGetSymbolAddress((void**)&pb_Wh2, g_Wh2_bf);
    cudaGetSymbolAddress((void**)&pb_WH, g_WH_bf);
    cudaGetSymbolAddress((void**)&pb_Wc, g_Wc_bf);
    cudaGetSymbolAddress((void**)&pb_Wfc, g_Wfc_bf);
    cudaGetSymbolAddress((void**)&pb_Wp, g_Wp_bf);
    cudaGetSymbolAddress((void**)&pb_Wg, g_Wg_bf);
    cudaGetSymbolAddress((void**)&pb_Ws, g_Ws_bf);
    cudaGetSymbolAddress((void**)&pb_hseq, g_hseq_bf);
    cudaGetSymbolAddress((void**)&pb_a, g_a_bf);
    cudaGetSymbolAddress((void**)&pb_ctxH, g_ctxH_bf);
    cudaGetSymbolAddress((void**)&pb_out, g_out_bf);
    cudaGetSymbolAddress((void**)&pb_Vfb, g_Vfb);
    cudaGetSymbolAddress((void**)&pb_H, g_H_bf);
    cudaGetSymbolAddress((void**)&pb_s, g_s_bf);

    // ---- conversions (single launch) ----
    {
        ConvSegs segs;
        const float* srcs[NSEG] = { image, Wa, Wih, Wx, Whh, Wh2, WH, Wc, Wfc, Wp, Wg, Ws };
        bf16* dsts[NSEG] = { pb_image, pb_Wa, pb_Wih, pb_Wx, pb_Whh, pb_Wh2, pb_WH,
                             pb_Wc, pb_Wfc, pb_Wp, pb_Wg, pb_Ws };
        int ns[NSEG] = { BB * NN * CC / 4, DD * CC / 4, 4 * DD * (DD + EE) / 4,
                         DD * (DD + EE) / 4, 4 * DD * DD / 4, DD * DD / 4, DD * DD / 4,
                         DD * DD / 4, DD * DD / 4, VOC * DD / 4, NN * DD / 4, NN * DD / 4 };
        int total4 = 0;
        for (int i = 0; i < NSEG; i++) { segs.src[i] = srcs[i]; segs.dst[i] = dsts[i]; segs.n4[i] = ns[i]; total4 += ns[i]; }
        f2bf_multi<<<(total4 + 255) / 256, 256>>>(segs, total4);
    }
    cat_bias3<<<(4 * DD + 255) / 256, 256>>>(bb, bhi, bmi, p_bcat, bih, bhh, p_bsum);

    // ---- precompute ----
    mean_kernel<<<(BB * CC + 255) / 256, 256>>>(image, pb_mean);
    tc(pb_image, CC, pb_Wa, CC, ba, p_Vf, pb_Vfb, DD, BB * NN / 128, DD, CC, 1);
    cat_w3<<<(3 * DD * CC + 255) / 256, 256>>>(Wb, Whi, Wmi, pb_Wcat);
    tc(pb_mean, CC, pb_Wcat, CC, p_bcat, p_init, nullptr, 3 * DD, 1, 3 * DD, CC, 1);
    split_init<<<(BB * DD + 255) / 256, 256>>>(p_vg, pb_hseq, p_m);
    {
        dim3 grid(1, 1, BB);
        gemm_nt<64, 64, 16, 4, 4><<<grid, 256>>>(p_Vf, DD, Wv, DD, p_zbase, NN,
                                                 NN, NN, DD,
                                                 (long long)NN * DD, 0, (long long)NN * NN);
    }
    xcat_build<<<(RR * (DD + EE) + 255) / 256, 256>>>(target, emb);
    tc(pb_xcat, DD + EE, pb_Wih, DD + EE, p_bsum, p_xg, nullptr, 4 * DD, RR / 128, 4 * DD, DD + EE, 0);
    tc(pb_xcat, DD + EE, pb_Wx, DD + EE, nullptr, p_xx, nullptr, DD, RR / 128, DD, DD + EE, 0);

    // ---- sequential recurrence: gates GEMM (BN=64, 32 CTAs) + elementwise ----
    for (int t = 0; t < TT; t++) {
        tc64(pb_hseq + (size_t)t * BB * DD, DD, pb_Whh, DD, nullptr, p_gates, nullptr,
             4 * DD, 1, 4 * DD, DD, 0);
        lstm_elem<<<(BB * DD + 255) / 256, 256>>>(p_xg + (size_t)t * BB * 4 * DD,
                                                  p_m,
                                                  pb_hseq + (size_t)(t + 1) * BB * DD,
                                                  p_tm + (size_t)t * BB * DD);
    }

    // ---- batched epilogue over RR rows ----
    const bf16* Hp = pb_hseq;
    const bf16* Hc = pb_hseq + (size_t)BB * DD;
    // a = sigmoid(xx + hp@Wh2^T) * tm   (fused into GEMM epilogue, act=3)
    tc(Hp, DD, pb_Wh2, DD, nullptr, nullptr, pb_a, DD, RR / 128, DD, DD, 3, p_xx, p_tm);
    tc(Hc, DD, pb_WH, DD, nullptr, p_H, pb_H, DD, RR / 128, DD, DD, 1);
    tc(pb_a, DD, pb_Wc, DD, bc, p_s, pb_s, DD, RR / 128, DD, DD, 1);
    // gH = H @ Wg^T ; sWs = s @ Ws^T  (BN=64 kernel, N=49)
    tc64(pb_H, DD, pb_Wg, DD, nullptr, p_gH, nullptr, NN, RR / 128, NN, DD, 0);
    tc64(pb_s, DD, pb_Ws, DD, nullptr, p_sWs, nullptr, NN, RR / 128, NN, DD, 0);
    attn_batched<<<RR, 256>>>(wh, out_attn);
    tc(pb_ctxH, DD, pb_Wfc, DD, bfc, p_out, pb_out, DD, RR / 128, DD, DD, 2);

    // ---- logits + log_softmax ----
    tc(pb_out, DD, pb_Wp, DD, bp, p_logits, nullptr, VOC, RR / 128, VOC, DD, 0);
    logsoftmax_kernel<<<RR, 512>>>(out);
}

// round 10
// speedup vs baseline: 1.3150x; 1.1193x over previous
#include <cuda_runtime.h>
#include <cuda_bf16.h>
#include <math.h>
#include <stdint.h>

#define BB 128
#define NN 49
#define CC 2048
#define DD 512
#define EE 512
#define VOC 10000
#define TT 20
#define RR (TT * BB)

typedef __nv_bfloat16 bf16;
typedef __nv_bfloat162 bf162;

// ---------------- fp32 scratch ----------------
__device__ float g_Vf[BB * NN * DD];
__device__ float g_zbase[BB * NN * NN];
__device__ float g_bcat[3 * DD];
__device__ float g_init[BB * 3 * DD];
__device__ float g_vg[BB * DD];
__device__ float g_m[BB * DD];
__device__ float g_tm[RR * DD];
__device__ float g_bsum[4 * DD];
__device__ float g_xg[RR * 4 * DD];
__device__ float g_xx[RR * DD];
__device__ float g_gates[BB * 4 * DD];
__device__ float g_H[RR * DD];
__device__ float g_s[RR * DD];
__device__ float g_gH[RR * NN];
__device__ float g_sWs[RR * NN];
__device__ float g_out[RR * DD];
__device__ float g_logits[(size_t)RR * VOC];

// ---------------- bf16 scratch ----------------
__device__ __align__(16) bf16 g_image_bf[BB * NN * CC];
__device__ __align__(16) bf16 g_Wa_bf[DD * CC];
__device__ __align__(16) bf16 g_mean_bf[BB * CC];
__device__ __align__(16) bf16 g_Wcat_bf[3 * DD * CC];
__device__ __align__(16) bf16 g_xcat_bf[RR * (DD + EE)];
__device__ __align__(16) bf16 g_Wih_bf[4 * DD * (DD + EE)];
__device__ __align__(16) bf16 g_Wx_bf[DD * (DD + EE)];
__device__ __align__(16) bf16 g_Whh_bf[4 * DD * DD];
__device__ __align__(16) bf16 g_Wh2_bf[DD * DD];
__device__ __align__(16) bf16 g_WH_bf[DD * DD];
__device__ __align__(16) bf16 g_Wc_bf[DD * DD];
__device__ __align__(16) bf16 g_Wfc_bf[DD * DD];
__device__ __align__(16) bf16 g_Wp_bf[VOC * DD];
__device__ __align__(16) bf16 g_Wg_bf[NN * DD];
__device__ __align__(16) bf16 g_Ws_bf[NN * DD];
__device__ __align__(16) bf16 g_hseq_bf[(TT + 1) * BB * DD];
__device__ __align__(16) bf16 g_a_bf[RR * DD];
__device__ __align__(16) bf16 g_ctxH_bf[RR * DD];
__device__ __align__(16) bf16 g_out_bf[RR * DD];
__device__ __align__(16) bf16 g_Vfb[BB * NN * DD];
__device__ __align__(16) bf16 g_H_bf[RR * DD];
__device__ __align__(16) bf16 g_s_bf[RR * DD];

__device__ __forceinline__ float sigmoidf_(float x) { return 1.f / (1.f + expf(-x)); }

__device__ __forceinline__ uint32_t smem_u32(const void* p) {
    uint32_t a;
    asm("{ .reg .u64 t; cvta.to.shared.u64 t, %1; cvt.u32.u64 %0, t; }" : "=r"(a) : "l"(p));
    return a;
}

__device__ __forceinline__ void cp_async16(uint32_t dst, const void* src, bool pred) {
    int sz = pred ? 16 : 0;
    asm volatile("cp.async.cg.shared.global [%0], [%1], 16, %2;"
                 :: "r"(dst), "l"(src), "r"(sz) : "memory");
}
#define CP_COMMIT() asm volatile("cp.async.commit_group;" ::: "memory")
#define CP_WAIT1()  asm volatile("cp.async.wait_group 1;" ::: "memory")

__device__ __forceinline__ void mma_bf16(float* c, const uint32_t* a, uint32_t b0, uint32_t b1)
{
    asm volatile(
        "mma.sync.aligned.m16n8k16.row.col.f32.bf16.bf16.f32 "
        "{%0,%1,%2,%3}, {%4,%5,%6,%7}, {%8,%9}, {%0,%1,%2,%3};"
        : "+f"(c[0]), "+f"(c[1]), "+f"(c[2]), "+f"(c[3])
        : "r"(a[0]), "r"(a[1]), "r"(a[2]), "r"(a[3]), "r"(b0), "r"(b1));
}

#define LDSM_X4(r0, r1, r2, r3, addr) \
    asm volatile("ldmatrix.sync.aligned.m8n8.x4.shared.b16 {%0,%1,%2,%3}, [%4];" \
        : "=r"(r0), "=r"(r1), "=r"(r2), "=r"(r3) : "r"(addr))

#define ASTR 40
#define ABUF (128 * ASTR)
#define SMEM_MM (4 * ABUF * 2)

// ==================== generic bf16 HMMA GEMM (BN=128, ldmatrix) ====================
// act: 0 none, 1 relu, 2 tanh, 3: Cb = bf16( sigmoid(aux1+v)*aux2 ) only.
__global__ void __launch_bounds__(256, 2) gemm_bf(
    const bf16* __restrict__ A, int lda,
    const bf16* __restrict__ B, int ldb,
    const float* __restrict__ bias,
    float* __restrict__ C, bf16* __restrict__ Cb, int ldc,
    int N, int K, int act,
    const float* __restrict__ aux1, const float* __restrict__ aux2)
{
    extern __shared__ bf16 sm[];
    const uint32_t sA_u[2] = { smem_u32(sm), smem_u32(sm + ABUF) };
    const uint32_t sB_u[2] = { smem_u32(sm + 2 * ABUF), smem_u32(sm + 3 * ABUF) };

    const int tid = threadIdx.x;
    const int wid = tid >> 5, lane = tid & 31;
    const int g = lane >> 2, tg = lane & 3;
    const int wm = (wid & 3) * 32;
    const int wn = (wid >> 2) * 64;
    const int m0 = blockIdx.y * 128;
    const int n0 = blockIdx.x * 128;

    A += (size_t)m0 * lda;

    float acc[2][8][4];
#pragma unroll
    for (int mi = 0; mi < 2; mi++)
#pragma unroll
        for (int ni = 0; ni < 8; ni++)
#pragma unroll
            for (int q = 0; q < 4; q++) acc[mi][ni][q] = 0.f;

    const int KI = K >> 5;
    const int r_ld = tid >> 2;
    const int c16 = tid & 3;

    // ldmatrix per-thread row/col offsets (lane>>3 selects matrix, lane&7 the row)
    const int lm_q = lane >> 3;
    const int lm_r = lane & 7;
    const int a_row = wm + (lm_q & 1) * 8 + lm_r;     // + mi*16
    const int a_col = (lm_q >> 1) * 8;                // + kb
    const int b_row = (lm_q >> 1) * 8 + lm_r;         // + wn + nip*16
    const int b_col = (lm_q & 1) * 8;                 // + kb

    {
#pragma unroll
        for (int j = 0; j < 2; j++) {
            int row = r_ld + j * 64;
            cp_async16(sA_u[0] + (row * ASTR + c16 * 8) * 2,
                       A + (size_t)row * lda + c16 * 8, true);
        }
#pragma unroll
        for (int j = 0; j < 2; j++) {
            int row = r_ld + j * 64;
            int gn = n0 + row;
            bool ok = gn < N;
            int gs = ok ? gn : (N - 1);
            cp_async16(sB_u[0] + (row * ASTR + c16 * 8) * 2,
                       B + (size_t)gs * ldb + c16 * 8, ok);
        }
        CP_COMMIT();
    }

    for (int i = 0; i < KI; i++) {
        const int cur = i & 1;
        if (i + 1 < KI) {
            const int nxt = cur ^ 1;
            const int k0 = (i + 1) << 5;
#pragma unroll
            for (int j = 0; j < 2; j++) {
                int row = r_ld + j * 64;
                cp_async16(sA_u[nxt] + (row * ASTR + c16 * 8) * 2,
                           A + (size_t)row * lda + k0 + c16 * 8, true);
            }
#pragma unroll
            for (int j = 0; j < 2; j++) {
                int row = r_ld + j * 64;
                int gn = n0 + row;
                bool ok = gn < N;
                int gs = ok ? gn : (N - 1);
                cp_async16(sB_u[nxt] + (row * ASTR + c16 * 8) * 2,
                           B + (size_t)gs * ldb + k0 + c16 * 8, ok);
            }
        }
        CP_COMMIT();
        CP_WAIT1();
        __syncthreads();

        const uint32_t sa = sA_u[cur];
        const uint32_t sb = sB_u[cur];
#pragma unroll
        for (int kk = 0; kk < 2; kk++) {
            const int kb = kk * 16;
            uint32_t a[2][4];
#pragma unroll
            for (int mi = 0; mi < 2; mi++) {
                uint32_t addr = sa + (((a_row + mi * 16) * ASTR) + kb + a_col) * 2;
                LDSM_X4(a[mi][0], a[mi][1], a[mi][2], a[mi][3], addr);
            }
#pragma unroll
            for (int nip = 0; nip < 4; nip++) {
                uint32_t b0, b1, b2, b3;
                uint32_t addr = sb + (((wn + nip * 16 + b_row) * ASTR) + kb + b_col) * 2;
                LDSM_X4(b0, b1, b2, b3, addr);
                mma_bf16(acc[0][2 * nip], a[0], b0, b1);
                mma_bf16(acc[1][2 * nip], a[1], b0, b1);
                mma_bf16(acc[0][2 * nip + 1], a[0], b2, b3);
                mma_bf16(acc[1][2 * nip + 1], a[1], b2, b3);
            }
        }
        __syncthreads();
    }

#pragma unroll
    for (int mi = 0; mi < 2; mi++) {
#pragma unroll
        for (int ni = 0; ni < 8; ni++) {
            int gr = m0 + wm + mi * 16 + g;
            int gc = n0 + wn + ni * 8 + 2 * tg;
#pragma unroll
            for (int q = 0; q < 4; q++) {
                int r = gr + (q >> 1) * 8;
                int c = gc + (q & 1);
                if (c < N) {
                    float v = acc[mi][ni][q];
                    size_t off = (size_t)r * ldc + c;
                    if (act == 3) {
                        float av = sigmoidf_(aux1[off] + v) * aux2[off];
                        Cb[off] = __float2bfloat16_rn(av);
                    } else {
                        if (bias) v += bias[c];
                        if (act == 1) v = fmaxf(v, 0.f);
                        else if (act == 2) v = tanhf(v);
                        C[off] = v;
                        if (Cb) Cb[off] = __float2bfloat16_rn(v);
                    }
                }
            }
        }
    }
}

// ==================== BN=64 bf16 HMMA GEMM (ldmatrix) ====================
#define BBUF64 (64 * ASTR)
#define SMEM_MM64 ((2 * ABUF + 2 * BBUF64) * 2)

__global__ void __launch_bounds__(256, 2) gemm_bf64(
    const bf16* __restrict__ A, int lda,
    const bf16* __restrict__ B, int ldb,
    const float* __restrict__ bias,
    float* __restrict__ C, bf16* __restrict__ Cb, int ldc,
    int N, int K, int act)
{
    extern __shared__ bf16 sm[];
    const uint32_t sA_u[2] = { smem_u32(sm), smem_u32(sm + ABUF) };
    const uint32_t sB_u[2] = { smem_u32(sm + 2 * ABUF), smem_u32(sm + 2 * ABUF + BBUF64) };

    const int tid = threadIdx.x;
    const int wid = tid >> 5, lane = tid & 31;
    const int g = lane >> 2, tg = lane & 3;
    const int wm = (wid & 3) * 32;
    const int wn = (wid >> 2) * 32;
    const int m0 = blockIdx.y * 128;
    const int n0 = blockIdx.x * 64;

    A += (size_t)m0 * lda;

    float acc[2][4][4];
#pragma unroll
    for (int mi = 0; mi < 2; mi++)
#pragma unroll
        for (int ni = 0; ni < 4; ni++)
#pragma unroll
            for (int q = 0; q < 4; q++) acc[mi][ni][q] = 0.f;

    const int KI = K >> 5;
    const int r_ld = tid >> 2;
    const int c16 = tid & 3;

    const int lm_q = lane >> 3;
    const int lm_r = lane & 7;
    const int a_row = wm + (lm_q & 1) * 8 + lm_r;
    const int a_col = (lm_q >> 1) * 8;
    const int b_row = (lm_q >> 1) * 8 + lm_r;
    const int b_col = (lm_q & 1) * 8;

    {
#pragma unroll
        for (int j = 0; j < 2; j++) {
            int row = r_ld + j * 64;
            cp_async16(sA_u[0] + (row * ASTR + c16 * 8) * 2,
                       A + (size_t)row * lda + c16 * 8, true);
        }
        {
            int row = r_ld;
            int gn = n0 + row;
            bool ok = (row < 64) && (gn < N);
            int gs = (gn < N) ? gn : (N - 1);
            if (row < 64)
                cp_async16(sB_u[0] + (row * ASTR + c16 * 8) * 2,
                           B + (size_t)gs * ldb + c16 * 8, ok);
        }
        CP_COMMIT();
    }

    for (int i = 0; i < KI; i++) {
        const int cur = i & 1;
        if (i + 1 < KI) {
            const int nxt = cur ^ 1;
            const int k0 = (i + 1) << 5;
#pragma unroll
            for (int j = 0; j < 2; j++) {
                int row = r_ld + j * 64;
                cp_async16(sA_u[nxt] + (row * ASTR + c16 * 8) * 2,
                           A + (size_t)row * lda + k0 + c16 * 8, true);
            }
            {
                int row = r_ld;
                int gn = n0 + row;
                bool ok = (row < 64) && (gn < N);
                int gs = (gn < N) ? gn : (N - 1);
                if (row < 64)
                    cp_async16(sB_u[nxt] + (row * ASTR + c16 * 8) * 2,
                               B + (size_t)gs * ldb + k0 + c16 * 8, ok);
            }
        }
        CP_COMMIT();
        CP_WAIT1();
        __syncthreads();

        const uint32_t sa = sA_u[cur];
        const uint32_t sb = sB_u[cur];
#pragma unroll
        for (int kk = 0; kk < 2; kk++) {
            const int kb = kk * 16;
            uint32_t a[2][4];
#pragma unroll
            for (int mi = 0; mi < 2; mi++) {
                uint32_t addr = sa + (((a_row + mi * 16) * ASTR) + kb + a_col) * 2;
                LDSM_X4(a[mi][0], a[mi][1], a[mi][2], a[mi][3], addr);
            }
#pragma unroll
            for (int nip = 0; nip < 2; nip++) {
                uint32_t b0, b1, b2, b3;
                uint32_t addr = sb + (((wn + nip * 16 + b_row) * ASTR) + kb + b_col) * 2;
                LDSM_X4(b0, b1, b2, b3, addr);
                mma_bf16(acc[0][2 * nip], a[0], b0, b1);
                mma_bf16(acc[1][2 * nip], a[1], b0, b1);
                mma_bf16(acc[0][2 * nip + 1], a[0], b2, b3);
                mma_bf16(acc[1][2 * nip + 1], a[1], b2, b3);
            }
        }
        __syncthreads();
    }

#pragma unroll
    for (int mi = 0; mi < 2; mi++) {
#pragma unroll
        for (int ni = 0; ni < 4; ni++) {
            int gr = m0 + wm + mi * 16 + g;
            int gc = n0 + wn + ni * 8 + 2 * tg;
#pragma unroll
            for (int q = 0; q < 4; q++) {
                int r = gr + (q >> 1) * 8;
                int c = gc + (q & 1);
                if (c < N) {
                    float v = acc[mi][ni][q];
                    if (bias) v += bias[c];
                    if (act == 1) v = fmaxf(v, 0.f);
                    else if (act == 2) v = tanhf(v);
                    C[(size_t)r * ldc + c] = v;
                    if (Cb) Cb[(size_t)r * ldc + c] = __float2bfloat16_rn(v);
                }
            }
        }
    }
}

// ==================== SIMT GEMM (zbase only) ====================
template <int BM, int BN, int BK, int TM, int TN>
__global__ void gemm_nt(const float* __restrict__ A, int lda,
                        const float* __restrict__ Bm, int ldb,
                        float* __restrict__ C, int ldc,
                        int M, int N, int K,
                        long long sA, long long sB, long long sC)
{
    constexpr int THREADS = (BM / TM) * (BN / TN);
    __shared__ float As[BK][BM + 4];
    __shared__ float Bs[BK][BN + 4];

    A += (long long)blockIdx.z * sA;
    Bm += (long long)blockIdx.z * sB;
    C += (long long)blockIdx.z * sC;

    const int tid = threadIdx.x;
    const int bm0 = blockIdx.y * BM;
    const int bn0 = blockIdx.x * BN;
    const int tm = (tid / (BN / TN)) * TM;
    const int tn = (tid % (BN / TN)) * TN;

    float acc[TM][TN];
#pragma unroll
    for (int i = 0; i < TM; i++)
#pragma unroll
        for (int j = 0; j < TN; j++) acc[i][j] = 0.f;

    for (int k0 = 0; k0 < K; k0 += BK) {
#pragma unroll
        for (int i = tid; i < BM * (BK / 4); i += THREADS) {
            int row = i / (BK / 4);
            int kc = i % (BK / 4);
            int gm = bm0 + row;
            int gk = k0 + kc * 4;
            float4 v = make_float4(0.f, 0.f, 0.f, 0.f);
            if (gm < M) v = *reinterpret_cast<const float4*>(A + (size_t)gm * lda + gk);
            As[kc * 4 + 0][row] = v.x; As[kc * 4 + 1][row] = v.y;
            As[kc * 4 + 2][row] = v.z; As[kc * 4 + 3][row] = v.w;
        }
#pragma unroll
        for (int i = tid; i < BN * (BK / 4); i += THREADS) {
            int row = i / (BK / 4);
            int kc = i % (BK / 4);
            int gn = bn0 + row;
            int gk = k0 + kc * 4;
            float4 v = make_float4(0.f, 0.f, 0.f, 0.f);
            if (gn < N) v = *reinterpret_cast<const float4*>(Bm + (size_t)gn * ldb + gk);
            Bs[kc * 4 + 0][row] = v.x; Bs[kc * 4 + 1][row] = v.y;
            Bs[kc * 4 + 2][row] = v.z; Bs[kc * 4 + 3][row] = v.w;
        }
        __syncthreads();
#pragma unroll
        for (int k = 0; k < BK; k++) {
            float ra[TM], rb[TN];
#pragma unroll
            for (int i = 0; i < TM; i++) ra[i] = As[k][tm + i];
#pragma unroll
            for (int j = 0; j < TN; j++) rb[j] = Bs[k][tn + j];
#pragma unroll
            for (int i = 0; i < TM; i++)
#pragma unroll
                for (int j = 0; j < TN; j++) acc[i][j] += ra[i] * rb[j];
        }
        __syncthreads();
    }

#pragma unroll
    for (int i = 0; i < TM; i++) {
        int gm = bm0 + tm + i;
        if (gm >= M) continue;
#pragma unroll
        for (int j = 0; j < TN; j++) {
            int gn = bn0 + tn + j;
            if (gn >= N) continue;
            C[(size_t)gm * ldc + gn] = acc[i][j];
        }
    }
}

// ==================== small kernels ====================
#define NSEG 12
struct ConvSegs {
    const float* src[NSEG];
    bf16* dst[NSEG];
    int n4[NSEG];
};

__global__ void f2bf_multi(ConvSegs segs, int total4)
{
    int i = blockIdx.x * blockDim.x + threadIdx.x;
    if (i >= total4) return;
    int idx = i;
#pragma unroll
    for (int s = 0; s < NSEG; s++) {
        if (idx < segs.n4[s]) {
            float4 v = reinterpret_cast<const float4*>(segs.src[s])[idx];
            bf162* o = reinterpret_cast<bf162*>(segs.dst[s]) + idx * 2;
            o[0] = __floats2bfloat162_rn(v.x, v.y);
            o[1] = __floats2bfloat162_rn(v.z, v.w);
            return;
        }
        idx -= segs.n4[s];
    }
}

__global__ void mean_kernel(const float* __restrict__ x, bf16* __restrict__ mean_bf)
{
    int idx = blockIdx.x * blockDim.x + threadIdx.x;
    if (idx >= BB * CC) return;
    int b = idx / CC, c = idx % CC;
    float acc = 0.f;
    const float* p = x + (size_t)b * NN * CC + c;
#pragma unroll 7
    for (int n = 0; n < NN; n++) acc += p[(size_t)n * CC];
    mean_bf[idx] = __float2bfloat16_rn(acc * (1.f / (float)NN));
}

__global__ void cat_w3(const float* __restrict__ Wb, const float* __restrict__ Whi,
                       const float* __restrict__ Wmi, bf16* __restrict__ Wcat)
{
    int idx = blockIdx.x * blockDim.x + threadIdx.x;
    if (idx >= 3 * DD * CC) return;
    int r = idx / CC;
    const float* src = (r < DD) ? Wb : (r < 2 * DD) ? Whi : Wmi;
    int rr = (r < DD) ? r : (r < 2 * DD) ? r - DD : r - 2 * DD;
    Wcat[idx] = __float2bfloat16_rn(src[(size_t)rr * CC + (idx % CC)]);
}

__global__ void cat_bias3(const float* __restrict__ bb, const float* __restrict__ bhi,
                          const float* __restrict__ bmi, float* __restrict__ bcat,
                          const float* __restrict__ bih, const float* __restrict__ bhh,
                          float* __restrict__ bsum)
{
    int i = blockIdx.x * blockDim.x + threadIdx.x;
    if (i < 3 * DD)
        bcat[i] = (i < DD) ? bb[i] : (i < 2 * DD) ? bhi[i - DD] : bmi[i - 2 * DD];
    if (i < 4 * DD)
        bsum[i] = bih[i] + bhh[i];
}

__global__ void split_init(float* __restrict__ vg, bf16* __restrict__ h0,
                           float* __restrict__ m0)
{
    int idx = blockIdx.x * blockDim.x + threadIdx.x;
    if (idx >= BB * DD) return;
    int b = idx >> 9, d = idx & (DD - 1);
    const float* row = g_init + (size_t)b * (3 * DD);
    vg[idx] = row[d];
    h0[idx] = __float2bfloat16_rn(row[DD + d]);
    m0[idx] = row[2 * DD + d];
}

__global__ void xcat_build(const int* __restrict__ target, const float* __restrict__ emb)
{
    int idx = blockIdx.x * blockDim.x + threadIdx.x;
    if (idx >= RR * (DD + EE)) return;
    int c = idx & 1023;
    int r = idx >> 10;
    int b = r % BB, t = r / BB;
    float v;
    if (c < DD) {
        v = g_vg[(size_t)b * DD + c];
    } else {
        v = 0.f;
        if (t > 0) v = emb[(size_t)target[b * TT + (t - 1)] * EE + (c - DD)];
    }
    g_xcat_bf[idx] = __float2bfloat16_rn(v);
}

__global__ void lstm_elem(const float* __restrict__ xg_t,
                          float* __restrict__ m,
                          bf16* __restrict__ h_out,
                          float* __restrict__ tm_out)
{
    int idx = blockIdx.x * blockDim.x + threadIdx.x;
    if (idx >= BB * DD) return;
    int b = idx >> 9, d = idx & (DD - 1);
    const float* gr = g_gates + (size_t)b * (4 * DD);
    const float* xr = xg_t + (size_t)b * (4 * DD);
    float gi = gr[d] + xr[d];
    float gf = gr[DD + d] + xr[DD + d];
    float gg = gr[2 * DD + d] + xr[2 * DD + d];
    float go = gr[3 * DD + d] + xr[3 * DD + d];
    float m2 = sigmoidf_(gf) * m[idx] + sigmoidf_(gi) * tanhf(gg);
    float tm2 = tanhf(m2);
    m[idx] = m2;
    h_out[idx] = __float2bfloat16_rn(sigmoidf_(go) * tm2);
    tm_out[idx] = tm2;
}

__global__ void attn_batched(const float* __restrict__ wh, float* __restrict__ out_attn)
{
    int r = blockIdx.x;
    int t = r / BB, b = r % BB;
    int tid = threadIdx.x;
    __shared__ float gHs[NN], whs[NN], zs[NN + 1], alphas[NN + 1];
    if (tid < NN) { gHs[tid] = g_gH[(size_t)r * NN + tid]; whs[tid] = wh[tid]; }
    __syncthreads();

    if (tid < NN) {
        const float* zb = g_zbase + ((size_t)b * NN + tid) * NN;
        float acc = 0.f;
        for (int k = 0; k < NN; k++) acc += tanhf(zb[k] + gHs[k]) * whs[k];
        zs[tid] = acc;
    } else if (tid == NN) {
        const float* sw = g_sWs + (size_t)r * NN;
        float acc = 0.f;
        for (int k = 0; k < NN; k++) acc += tanhf(sw[k] + gHs[k]) * whs[k];
        zs[NN] = acc;
    }
    __syncthreads();

    if (tid == 0) {
        float mx = -1e30f;
        for (int i = 0; i <= NN; i++) mx = fmaxf(mx, zs[i]);
        float sum = 0.f;
        for (int i = 0; i <= NN; i++) { float e = expf(zs[i] - mx); alphas[i] = e; sum += e; }
        float inv = 1.f / sum;
        for (int i = 0; i <= NN; i++) alphas[i] *= inv;
    }
    __syncthreads();

    if (tid < NN) out_attn[((size_t)b * TT + t) * NN + tid] = alphas[tid];

    {
        int d = tid * 2;
        float aN = alphas[NN];
        float cx = aN * g_s[(size_t)r * DD + d];
        float cy = aN * g_s[(size_t)r * DD + d + 1];
        const bf162* vf = reinterpret_cast<const bf162*>(g_Vfb + (size_t)b * NN * DD + d);
#pragma unroll 7
        for (int n = 0; n < NN; n++) {
            float2 v = __bfloat1622float2(vf[n * (DD / 2)]);
            cx += alphas[n] * v.x;
            cy += alphas[n] * v.y;
        }
        cx += g_H[(size_t)r * DD + d];
        cy += g_H[(size_t)r * DD + d + 1];
        reinterpret_cast<bf162*>(g_ctxH_bf + (size_t)r * DD + d)[0] =
            __floats2bfloat162_rn(cx, cy);
    }
}

__global__ void logsoftmax_kernel(float* __restrict__ out)
{
    int r = blockIdx.x;
    int t = r / BB, b = r % BB;
    const float4* row = reinterpret_cast<const float4*>(g_logits + (size_t)r * VOC);
    const int NV = VOC / 4;
    __shared__ float red[512];
    float mx = -1e30f;
    for (int v = threadIdx.x; v < NV; v += 512) {
        float4 x = row[v];
        mx = fmaxf(mx, fmaxf(fmaxf(x.x, x.y), fmaxf(x.z, x.w)));
    }
    red[threadIdx.x] = mx; __syncthreads();
    for (int s = 256; s > 0; s >>= 1) {
        if (threadIdx.x < s) red[threadIdx.x] = fmaxf(red[threadIdx.x], red[threadIdx.x + s]);
        __syncthreads();
    }
    mx = red[0]; __syncthreads();
    float sum = 0.f;
    for (int v = threadIdx.x; v < NV; v += 512) {
        float4 x = row[v];
        sum += expf(x.x - mx) + expf(x.y - mx) + expf(x.z - mx) + expf(x.w - mx);
    }
    red[threadIdx.x] = sum; __syncthreads();
    for (int s = 256; s > 0; s >>= 1) {
        if (threadIdx.x < s) red[threadIdx.x] += red[threadIdx.x + s];
        __syncthreads();
    }
    float lse = mx + logf(red[0]);
    float4* orow = reinterpret_cast<float4*>(out + ((size_t)b * TT + t) * VOC);
    for (int v = threadIdx.x; v < NV; v += 512) {
        float4 x = row[v];
        orow[v] = make_float4(x.x - lse, x.y - lse, x.z - lse, x.w - lse);
    }
}

// ==================== host ====================
static inline void tc(const bf16* A, int lda, const bf16* B, int ldb,
                      const float* bias, float* C, bf16* Cb, int ldc,
                      int Mtiles, int N, int K, int act,
                      const float* aux1 = nullptr, const float* aux2 = nullptr)
{
    dim3 grid((N + 127) / 128, Mtiles);
    gemm_bf<<<grid, 256, SMEM_MM>>>(A, lda, B, ldb, bias, C, Cb, ldc, N, K, act, aux1, aux2);
}

static inline void tc64(const bf16* A, int lda, const bf16* B, int ldb,
                        const float* bias, float* C, bf16* Cb, int ldc,
                        int Mtiles, int N, int K, int act)
{
    dim3 grid((N + 63) / 64, Mtiles);
    gemm_bf64<<<grid, 256, SMEM_MM64>>>(A, lda, B, ldb, bias, C, Cb, ldc, N, K, act);
}

extern "C" void kernel_launch(void* const* d_in, const int* in_sizes, int n_in,
                              void* d_out, int out_size)
{
    const float* image = (const float*)d_in[0];
    const int*   target = (const int*)d_in[1];
    const float* emb = (const float*)d_in[2];
    const float* Wa = (const float*)d_in[3];  const float* ba = (const float*)d_in[4];
    const float* Wb = (const float*)d_in[5];  const float* bb = (const float*)d_in[6];
    const float* Whi = (const float*)d_in[7]; const float* bhi = (const float*)d_in[8];
    const float* Wmi = (const float*)d_in[9]; const float* bmi = (const float*)d_in[10];
    const float* Wih = (const float*)d_in[11]; const float* bih = (const float*)d_in[12];
    const float* Whh = (const float*)d_in[13]; const float* bhh = (const float*)d_in[14];
    const float* Wv = (const float*)d_in[15];
    const float* Wg = (const float*)d_in[16];
    const float* wh = (const float*)d_in[17];
    const float* WH = (const float*)d_in[18];
    const float* Wx = (const float*)d_in[19];
    const float* Wh2 = (const float*)d_in[20];
    const float* Ws = (const float*)d_in[21];
    const float* Wc = (const float*)d_in[22]; const float* bc = (const float*)d_in[23];
    const float* Wfc = (const float*)d_in[24]; const float* bfc = (const float*)d_in[25];
    const float* Wp = (const float*)d_in[26]; const float* bp = (const float*)d_in[27];

    float* out = (float*)d_out;
    float* out_attn = out + (size_t)BB * TT * VOC;

    float *p_Vf, *p_zbase, *p_bcat, *p_vg, *p_m, *p_tm, *p_bsum, *p_xg, *p_xx, *p_gates;
    float *p_H, *p_s, *p_gH, *p_sWs, *p_out, *p_logits, *p_init;
    bf16 *pb_image, *pb_Wa, *pb_mean, *pb_Wcat, *pb_xcat, *pb_Wih, *pb_Wx, *pb_Whh;
    bf16 *pb_Wh2, *pb_WH, *pb_Wc, *pb_Wfc, *pb_Wp, *pb_Wg, *pb_Ws;
    bf16 *pb_hseq, *pb_a, *pb_ctxH, *pb_out, *pb_Vfb, *pb_H, *pb_s;
    cudaGetSymbolAddress((void**)&p_Vf, g_Vf);
    cudaGetSymbolAddress((void**)&p_zbase, g_zbase);
    cudaGetSymbolAddress((void**)&p_bcat, g_bcat);
    cudaGetSymbolAddress((void**)&p_init, g_init);
    cudaGetSymbolAddress((void**)&p_vg, g_vg);
    cudaGetSymbolAddress((void**)&p_m, g_m);
    cudaGetSymbolAddress((void**)&p_tm, g_tm);
    cudaGetSymbolAddress((void**)&p_bsum, g_bsum);
    cudaGetSymbolAddress((void**)&p_xg, g_xg);
    cudaGetSymbolAddress((void**)&p_xx, g_xx);
    cudaGetSymbolAddress((void**)&p_gates, g_gates);
    cudaGetSymbolAddress((void**)&p_H, g_H);
    cudaGetSymbolAddress((void**)&p_s, g_s);
    cudaGetSymbolAddress((void**)&p_gH, g_gH);
    cudaGetSymbolAddress((void**)&p_sWs, g_sWs);
    cudaGetSymbolAddress((void**)&p_out, g_out);
    cudaGetSymbolAddress((void**)&p_logits, g_logits);
    cudaGetSymbolAddress((void**)&pb_image, g_image_bf);
    cudaGetSymbolAddress((void**)&pb_Wa, g_Wa_bf);
    cudaGetSymbolAddress((void**)&pb_mean, g_mean_bf);
    cudaGetSymbolAddress((void**)&pb_Wcat, g_Wcat_bf);
    cudaGetSymbolAddress((void**)&pb_xcat, g_xcat_bf);
    cudaGetSymbolAddress((void**)&pb_Wih, g_Wih_bf);
    cudaGetSymbolAddress((void**)&pb_Wx, g_Wx_bf);
    cudaGetSymbolAddress((void**)&pb_Whh, g_Whh_bf);
    cudaGetSymbolAddress((void**)&pb_Wh2, g_Wh2_bf);
    cudaGetSymbolAddress((void**)&pb_WH, g_WH_bf);
    cudaGetSymbolAddress((void**)&pb_Wc, g_Wc_bf);
    cudaGetSymbolAddress((void**)&pb_Wfc, g_Wfc_bf);
    cudaGetSymbolAddress((void**)&pb_Wp, g_Wp_bf);
    cudaGetSymbolAddress((void**)&pb_Wg, g_Wg_bf);
    cudaGetSymbolAddress((void**)&pb_Ws, g_Ws_bf);
    cudaGetSymbolAddress((void**)&pb_hseq, g_hseq_bf);
    cudaGetSymbolAddress((void**)&pb_a, g_a_bf);
    cudaGetSymbolAddress((void**)&pb_ctxH, g_ctxH_bf);
    cudaGetSymbolAddress((void**)&pb_out, g_out_bf);
    cudaGetSymbolAddress((void**)&pb_Vfb, g_Vfb);
    cudaGetSymbolAddress((void**)&pb_H, g_H_bf);
    cudaGetSymbolAddress((void**)&pb_s, g_s_bf);

    // ---- conversions (single launch) ----
    {
        ConvSegs segs;
        const float* srcs[NSEG] = { image, Wa, Wih, Wx, Whh, Wh2, WH, Wc, Wfc, Wp, Wg, Ws };
        bf16* dsts[NSEG] = { pb_image, pb_Wa, pb_Wih, pb_Wx, pb_Whh, pb_Wh2, pb_WH,
                             pb_Wc, pb_Wfc, pb_Wp, pb_Wg, pb_Ws };
        int ns[NSEG] = { BB * NN * CC / 4, DD * CC / 4, 4 * DD * (DD + EE) / 4,
                         DD * (DD + EE) / 4, 4 * DD * DD / 4, DD * DD / 4, DD * DD / 4,
                         DD * DD / 4, DD * DD / 4, VOC * DD / 4, NN * DD / 4, NN * DD / 4 };
        int total4 = 0;
        for (int i = 0; i < NSEG; i++) { segs.src[i] = srcs[i]; segs.dst[i] = dsts[i]; segs.n4[i] = ns[i]; total4 += ns[i]; }
        f2bf_multi<<<(total4 + 255) / 256, 256>>>(segs, total4);
    }
    cat_bias3<<<(4 * DD + 255) / 256, 256>>>(bb, bhi, bmi, p_bcat, bih, bhh, p_bsum);

    // ---- precompute ----
    mean_kernel<<<(BB * CC + 255) / 256, 256>>>(image, pb_mean);
    tc(pb_image, CC, pb_Wa, CC, ba, p_Vf, pb_Vfb, DD, BB * NN / 128, DD, CC, 1);
    cat_w3<<<(3 * DD * CC + 255) / 256, 256>>>(Wb, Whi, Wmi, pb_Wcat);
    tc(pb_mean, CC, pb_Wcat, CC, p_bcat, p_init, nullptr, 3 * DD, 1, 3 * DD, CC, 1);
    split_init<<<(BB * DD + 255) / 256, 256>>>(p_vg, pb_hseq, p_m);
    {
        dim3 grid(1, 1, BB);
        gemm_nt<64, 64, 16, 4, 4><<<grid, 256>>>(p_Vf, DD, Wv, DD, p_zbase, NN,
                                                 NN, NN, DD,
                                                 (long long)NN * DD, 0, (long long)NN * NN);
    }
    xcat_build<<<(RR * (DD + EE) + 255) / 256, 256>>>(target, emb);
    tc(pb_xcat, DD + EE, pb_Wih, DD + EE, p_bsum, p_xg, nullptr, 4 * DD, RR / 128, 4 * DD, DD + EE, 0);
    tc(pb_xcat, DD + EE, pb_Wx, DD + EE, nullptr, p_xx, nullptr, DD, RR / 128, DD, DD + EE, 0);

    // ---- sequential recurrence: gates GEMM (BN=64, 32 CTAs) + elementwise ----
    for (int t = 0; t < TT; t++) {
        tc64(pb_hseq + (size_t)t * BB * DD, DD, pb_Whh, DD, nullptr, p_gates, nullptr,
             4 * DD, 1, 4 * DD, DD, 0);
        lstm_elem<<<(BB * DD + 255) / 256, 256>>>(p_xg + (size_t)t * BB * 4 * DD,
                                                  p_m,
                                                  pb_hseq + (size_t)(t + 1) * BB * DD,
                                                  p_tm + (size_t)t * BB * DD);
    }

    // ---- batched epilogue over RR rows ----
    const bf16* Hp = pb_hseq;
    const bf16* Hc = pb_hseq + (size_t)BB * DD;
    tc(Hp, DD, pb_Wh2, DD, nullptr, nullptr, pb_a, DD, RR / 128, DD, DD, 3, p_xx, p_tm);
    tc(Hc, DD, pb_WH, DD, nullptr, p_H, pb_H, DD, RR / 128, DD, DD, 1);
    tc(pb_a, DD, pb_Wc, DD, bc, p_s, pb_s, DD, RR / 128, DD, DD, 1);
    tc64(pb_H, DD, pb_Wg, DD, nullptr, p_gH, nullptr, NN, RR / 128, NN, DD, 0);
    tc64(pb_s, DD, pb_Ws, DD, nullptr, p_sWs, nullptr, NN, RR / 128, NN, DD, 0);
    attn_batched<<<RR, 256>>>(wh, out_attn);
    tc(pb_ctxH, DD, pb_Wfc, DD, bfc, p_out, pb_out, DD, RR / 128, DD, DD, 2);

    // ---- logits + log_softmax ----
    tc(pb_out, DD, pb_Wp, DD, bp, p_logits, nullptr, VOC, RR / 128, VOC, DD, 0);
    logsoftmax_kernel<<<RR, 512>>>(out);
}

// round 13
// speedup vs baseline: 1.4257x; 1.0841x over previous
#include <cuda_runtime.h>
#include <cuda_bf16.h>
#include <math.h>
#include <stdint.h>

#define BB 128
#define NN 49
#define CC 2048
#define DD 512
#define EE 512
#define VOC 10000
#define TT 20
#define RR (TT * BB)

typedef __nv_bfloat16 bf16;
typedef __nv_bfloat162 bf162;

// ---------------- fp32 scratch ----------------
__device__ float g_Vf[BB * NN * DD];
__device__ float g_zbase[BB * NN * NN];
__device__ float g_bcat[3 * DD];
__device__ float g_init[BB * 3 * DD];
__device__ float g_vg[BB * DD];
__device__ float g_m[BB * DD];
__device__ float g_tm[RR * DD];
__device__ float g_bsum[4 * DD];
__device__ float g_xg[RR * 4 * DD];
__device__ float g_xx[RR * DD];
__device__ float g_gates[BB * 4 * DD];
__device__ float g_H[RR * DD];
__device__ float g_s[RR * DD];
__device__ float g_gH[RR * NN];
__device__ float g_sWs[RR * NN];
__device__ float g_out[RR * DD];
__device__ float g_logits[(size_t)RR * VOC];

// ---------------- bf16 scratch ----------------
__device__ __align__(16) bf16 g_image_bf[BB * NN * CC];
__device__ __align__(16) bf16 g_Wa_bf[DD * CC];
__device__ __align__(16) bf16 g_mean_bf[BB * CC];
__device__ __align__(16) bf16 g_Wcat_bf[3 * DD * CC];
__device__ __align__(16) bf16 g_xcat_bf[RR * (DD + EE)];
__device__ __align__(16) bf16 g_Wih_bf[4 * DD * (DD + EE)];
__device__ __align__(16) bf16 g_Wx_bf[DD * (DD + EE)];
__device__ __align__(16) bf16 g_Whh_bf[4 * DD * DD];
__device__ __align__(16) bf16 g_Wh2_bf[DD * DD];
__device__ __align__(16) bf16 g_WH_bf[DD * DD];
__device__ __align__(16) bf16 g_Wc_bf[DD * DD];
__device__ __align__(16) bf16 g_Wfc_bf[DD * DD];
__device__ __align__(16) bf16 g_Wp_bf[VOC * DD];
__device__ __align__(16) bf16 g_Wg_bf[NN * DD];
__device__ __align__(16) bf16 g_Ws_bf[NN * DD];
__device__ __align__(16) bf16 g_hseq_bf[(TT + 1) * BB * DD];
__device__ __align__(16) bf16 g_a_bf[RR * DD];
__device__ __align__(16) bf16 g_ctxH_bf[RR * DD];
__device__ __align__(16) bf16 g_out_bf[RR * DD];
__device__ __align__(16) bf16 g_Vfb[BB * NN * DD];
__device__ __align__(16) bf16 g_H_bf[RR * DD];
__device__ __align__(16) bf16 g_s_bf[RR * DD];

__device__ __forceinline__ float sigmoidf_(float x) { return 1.f / (1.f + expf(-x)); }

__device__ __forceinline__ uint32_t smem_u32(const void* p) {
    uint32_t a;
    asm("{ .reg .u64 t; cvta.to.shared.u64 t, %1; cvt.u32.u64 %0, t; }" : "=r"(a) : "l"(p));
    return a;
}

__device__ __forceinline__ void cp_async16(uint32_t dst, const void* src, bool pred) {
    int sz = pred ? 16 : 0;
    asm volatile("cp.async.cg.shared.global [%0], [%1], 16, %2;"
                 :: "r"(dst), "l"(src), "r"(sz) : "memory");
}
#define CP_COMMIT() asm volatile("cp.async.commit_group;" ::: "memory")
#define CP_WAIT1()  asm volatile("cp.async.wait_group 1;" ::: "memory")

__device__ __forceinline__ void mma_bf16(float* c, const uint32_t* a, uint32_t b0, uint32_t b1)
{
    asm volatile(
        "mma.sync.aligned.m16n8k16.row.col.f32.bf16.bf16.f32 "
        "{%0,%1,%2,%3}, {%4,%5,%6,%7}, {%8,%9}, {%0,%1,%2,%3};"
        : "+f"(c[0]), "+f"(c[1]), "+f"(c[2]), "+f"(c[3])
        : "r"(a[0]), "r"(a[1]), "r"(a[2]), "r"(a[3]), "r"(b0), "r"(b1));
}

#define LDSM_X4(r0, r1, r2, r3, addr) \
    asm volatile("ldmatrix.sync.aligned.m8n8.x4.shared.b16 {%0,%1,%2,%3}, [%4];" \
        : "=r"(r0), "=r"(r1), "=r"(r2), "=r"(r3) : "r"(addr))

// BK=64 tiling: row stride 72 bf16 (144 B = 9*16, aligned; ldmatrix bank-clean)
#define ASTR 72
#define ABUF (128 * ASTR)
#define BBUF64 (64 * ASTR)
#define SMEM_MM (4 * ABUF * 2)                  // 73728 B
#define SMEM_MM64 ((2 * ABUF + 2 * BBUF64) * 2) // 55296 B

// ==================== generic bf16 HMMA GEMM (BN=128, BK=64, ldmatrix) ====================
// act: 0 none, 1 relu, 2 tanh, 3: Cb = bf16( sigmoid(aux1+v)*aux2 ) only.
__global__ void __launch_bounds__(256, 2) gemm_bf(
    const bf16* __restrict__ A, int lda,
    const bf16* __restrict__ B, int ldb,
    const float* __restrict__ bias,
    float* __restrict__ C, bf16* __restrict__ Cb, int ldc,
    int N, int K, int act,
    const float* __restrict__ aux1, const float* __restrict__ aux2)
{
    extern __shared__ bf16 sm[];
    const uint32_t sA_u[2] = { smem_u32(sm), smem_u32(sm + ABUF) };
    const uint32_t sB_u[2] = { smem_u32(sm + 2 * ABUF), smem_u32(sm + 3 * ABUF) };

    const int tid = threadIdx.x;
    const int wid = tid >> 5, lane = tid & 31;
    const int g = lane >> 2, tg = lane & 3;
    const int wm = (wid & 3) * 32;
    const int wn = (wid >> 2) * 64;
    const int m0 = blockIdx.y * 128;
    const int n0 = blockIdx.x * 128;

    A += (size_t)m0 * lda;

    float acc[2][8][4];
#pragma unroll
    for (int mi = 0; mi < 2; mi++)
#pragma unroll
        for (int ni = 0; ni < 8; ni++)
#pragma unroll
            for (int q = 0; q < 4; q++) acc[mi][ni][q] = 0.f;

    const int KI = K >> 6;

    const int lm_q = lane >> 3;
    const int lm_r = lane & 7;
    const int a_row = wm + (lm_q & 1) * 8 + lm_r;
    const int a_col = (lm_q >> 1) * 8;
    const int b_row = (lm_q >> 1) * 8 + lm_r;
    const int b_col = (lm_q & 1) * 8;

    {
#pragma unroll
        for (int j = 0; j < 4; j++) {
            int pos = tid + j * 256;
            int row = pos >> 3, c8 = pos & 7;
            cp_async16(sA_u[0] + (row * ASTR + c8 * 8) * 2,
                       A + (size_t)row * lda + c8 * 8, true);
        }
#pragma unroll
        for (int j = 0; j < 4; j++) {
            int pos = tid + j * 256;
            int row = pos >> 3, c8 = pos & 7;
            int gn = n0 + row;
            bool ok = gn < N;
            int gs = ok ? gn : (N - 1);
            cp_async16(sB_u[0] + (row * ASTR + c8 * 8) * 2,
                       B + (size_t)gs * ldb + c8 * 8, ok);
        }
        CP_COMMIT();
    }

    for (int i = 0; i < KI; i++) {
        const int cur = i & 1;
        if (i + 1 < KI) {
            const int nxt = cur ^ 1;
            const int k0 = (i + 1) << 6;
#pragma unroll
            for (int j = 0; j < 4; j++) {
                int pos = tid + j * 256;
                int row = pos >> 3, c8 = pos & 7;
                cp_async16(sA_u[nxt] + (row * ASTR + c8 * 8) * 2,
                           A + (size_t)row * lda + k0 + c8 * 8, true);
            }
#pragma unroll
            for (int j = 0; j < 4; j++) {
                int pos = tid + j * 256;
                int row = pos >> 3, c8 = pos & 7;
                int gn = n0 + row;
                bool ok = gn < N;
                int gs = ok ? gn : (N - 1);
                cp_async16(sB_u[nxt] + (row * ASTR + c8 * 8) * 2,
                           B + (size_t)gs * ldb + k0 + c8 * 8, ok);
            }
        }
        CP_COMMIT();
        CP_WAIT1();
        __syncthreads();

        const uint32_t sa = sA_u[cur];
        const uint32_t sb = sB_u[cur];
#pragma unroll
        for (int kk = 0; kk < 4; kk++) {
            const int kb = kk * 16;
            uint32_t a[2][4];
#pragma unroll
            for (int mi = 0; mi < 2; mi++) {
                uint32_t addr = sa + (((a_row + mi * 16) * ASTR) + kb + a_col) * 2;
                LDSM_X4(a[mi][0], a[mi][1], a[mi][2], a[mi][3], addr);
            }
#pragma unroll
            for (int nip = 0; nip < 4; nip++) {
                uint32_t b0, b1, b2, b3;
                uint32_t addr = sb + (((wn + nip * 16 + b_row) * ASTR) + kb + b_col) * 2;
                LDSM_X4(b0, b1, b2, b3, addr);
                mma_bf16(acc[0][2 * nip], a[0], b0, b1);
                mma_bf16(acc[1][2 * nip], a[1], b0, b1);
                mma_bf16(acc[0][2 * nip + 1], a[0], b2, b3);
                mma_bf16(acc[1][2 * nip + 1], a[1], b2, b3);
            }
        }
        __syncthreads();
    }

#pragma unroll
    for (int mi = 0; mi < 2; mi++) {
#pragma unroll
        for (int ni = 0; ni < 8; ni++) {
            int gr = m0 + wm + mi * 16 + g;
            int gc = n0 + wn + ni * 8 + 2 * tg;
#pragma unroll
            for (int qr = 0; qr < 2; qr++) {
                int r = gr + qr * 8;
                float v0 = acc[mi][ni][qr * 2 + 0];
                float v1 = acc[mi][ni][qr * 2 + 1];
                size_t off = (size_t)r * ldc + gc;
                bool aligned = ((off & 1) == 0);
                if (act == 3) {
                    if (gc + 1 < N) {
                        float a0 = sigmoidf_(aux1[off] + v0) * aux2[off];
                        float a1 = sigmoidf_(aux1[off + 1] + v1) * aux2[off + 1];
                        if (aligned) {
                            *reinterpret_cast<bf162*>(Cb + off) = __floats2bfloat162_rn(a0, a1);
                        } else {
                            Cb[off] = __float2bfloat16_rn(a0);
                            Cb[off + 1] = __float2bfloat16_rn(a1);
                        }
                    } else if (gc < N) {
                        Cb[off] = __float2bfloat16_rn(sigmoidf_(aux1[off] + v0) * aux2[off]);
                    }
                } else {
                    if (bias) { v0 += bias[gc]; if (gc + 1 < N) v1 += bias[gc + 1]; }
                    if (act == 1) { v0 = fmaxf(v0, 0.f); v1 = fmaxf(v1, 0.f); }
                    else if (act == 2) { v0 = tanhf(v0); v1 = tanhf(v1); }
                    if (gc + 1 < N) {
                        if (aligned) {
                            *reinterpret_cast<float2*>(C + off) = make_float2(v0, v1);
                            if (Cb) *reinterpret_cast<bf162*>(Cb + off) = __floats2bfloat162_rn(v0, v1);
                        } else {
                            C[off] = v0; C[off + 1] = v1;
                            if (Cb) {
                                Cb[off] = __float2bfloat16_rn(v0);
                                Cb[off + 1] = __float2bfloat16_rn(v1);
                            }
                        }
                    } else if (gc < N) {
                        C[off] = v0;
                        if (Cb) Cb[off] = __float2bfloat16_rn(v0);
                    }
                }
            }
        }
    }
}

// ==================== BN=64, BK=64 bf16 HMMA GEMM (ldmatrix) ====================
__global__ void __launch_bounds__(256, 2) gemm_bf64(
    const bf16* __restrict__ A, int lda,
    const bf16* __restrict__ B, int ldb,
    const float* __restrict__ bias,
    float* __restrict__ C, bf16* __restrict__ Cb, int ldc,
    int N, int K, int act)
{
    extern __shared__ bf16 sm[];
    const uint32_t sA_u[2] = { smem_u32(sm), smem_u32(sm + ABUF) };
    const uint32_t sB_u[2] = { smem_u32(sm + 2 * ABUF), smem_u32(sm + 2 * ABUF + BBUF64) };

    const int tid = threadIdx.x;
    const int wid = tid >> 5, lane = tid & 31;
    const int g = lane >> 2, tg = lane & 3;
    const int wm = (wid & 3) * 32;
    const int wn = (wid >> 2) * 32;
    const int m0 = blockIdx.y * 128;
    const int n0 = blockIdx.x * 64;

    A += (size_t)m0 * lda;

    float acc[2][4][4];
#pragma unroll
    for (int mi = 0; mi < 2; mi++)
#pragma unroll
        for (int ni = 0; ni < 4; ni++)
#pragma unroll
            for (int q = 0; q < 4; q++) acc[mi][ni][q] = 0.f;

    const int KI = K >> 6;

    const int lm_q = lane >> 3;
    const int lm_r = lane & 7;
    const int a_row = wm + (lm_q & 1) * 8 + lm_r;
    const int a_col = (lm_q >> 1) * 8;
    const int b_row = (lm_q >> 1) * 8 + lm_r;
    const int b_col = (lm_q & 1) * 8;

    {
#pragma unroll
        for (int j = 0; j < 4; j++) {
            int pos = tid + j * 256;
            int row = pos >> 3, c8 = pos & 7;
            cp_async16(sA_u[0] + (row * ASTR + c8 * 8) * 2,
                       A + (size_t)row * lda + c8 * 8, true);
        }
#pragma unroll
        for (int j = 0; j < 2; j++) {
            int pos = tid + j * 256;
            int row = pos >> 3, c8 = pos & 7;
            int gn = n0 + row;
            bool ok = gn < N;
            int gs = ok ? gn : (N - 1);
            cp_async16(sB_u[0] + (row * ASTR + c8 * 8) * 2,
                       B + (size_t)gs * ldb + c8 * 8, ok);
        }
        CP_COMMIT();
    }

    for (int i = 0; i < KI; i++) {
        const int cur = i & 1;
        if (i + 1 < KI) {
            const int nxt = cur ^ 1;
            const int k0 = (i + 1) << 6;
#pragma unroll
            for (int j = 0; j < 4; j++) {
                int pos = tid + j * 256;
                int row = pos >> 3, c8 = pos & 7;
                cp_async16(sA_u[nxt] + (row * ASTR + c8 * 8) * 2,
                           A + (size_t)row * lda + k0 + c8 * 8, true);
            }
#pragma unroll
            for (int j = 0; j < 2; j++) {
                int pos = tid + j * 256;
                int row = pos >> 3, c8 = pos & 7;
                int gn = n0 + row;
                bool ok = gn < N;
                int gs = ok ? gn : (N - 1);
                cp_async16(sB_u[nxt] + (row * ASTR + c8 * 8) * 2,
                           B + (size_t)gs * ldb + k0 + c8 * 8, ok);
            }
        }
        CP_COMMIT();
        CP_WAIT1();
        __syncthreads();

        const uint32_t sa = sA_u[cur];
        const uint32_t sb = sB_u[cur];
#pragma unroll
        for (int kk = 0; kk < 4; kk++) {
            const int kb = kk * 16;
            uint32_t a[2][4];
#pragma unroll
            for (int mi = 0; mi < 2; mi++) {
                uint32_t addr = sa + (((a_row + mi * 16) * ASTR) + kb + a_col) * 2;
                LDSM_X4(a[mi][0], a[mi][1], a[mi][2], a[mi][3], addr);
            }
#pragma unroll
            for (int nip = 0; nip < 2; nip++) {
                uint32_t b0, b1, b2, b3;
                uint32_t addr = sb + (((wn + nip * 16 + b_row) * ASTR) + kb + b_col) * 2;
                LDSM_X4(b0, b1, b2, b3, addr);
                mma_bf16(acc[0][2 * nip], a[0], b0, b1);
                mma_bf16(acc[1][2 * nip], a[1], b0, b1);
                mma_bf16(acc[0][2 * nip + 1], a[0], b2, b3);
                mma_bf16(acc[1][2 * nip + 1], a[1], b2, b3);
            }
        }
        __syncthreads();
    }

#pragma unroll
    for (int mi = 0; mi < 2; mi++) {
#pragma unroll
        for (int ni = 0; ni < 4; ni++) {
            int gr = m0 + wm + mi * 16 + g;
            int gc = n0 + wn + ni * 8 + 2 * tg;
#pragma unroll
            for (int qr = 0; qr < 2; qr++) {
                int r = gr + qr * 8;
                float v0 = acc[mi][ni][qr * 2 + 0];
                float v1 = acc[mi][ni][qr * 2 + 1];
                size_t off = (size_t)r * ldc + gc;
                bool aligned = ((off & 1) == 0);
                if (bias) { v0 += bias[gc]; if (gc + 1 < N) v1 += bias[gc + 1]; }
                if (act == 1) { v0 = fmaxf(v0, 0.f); v1 = fmaxf(v1, 0.f); }
                else if (act == 2) { v0 = tanhf(v0); v1 = tanhf(v1); }
                if (gc + 1 < N) {
                    if (aligned) {
                        *reinterpret_cast<float2*>(C + off) = make_float2(v0, v1);
                        if (Cb) *reinterpret_cast<bf162*>(Cb + off) = __floats2bfloat162_rn(v0, v1);
                    } else {
                        C[off] = v0; C[off + 1] = v1;
                        if (Cb) {
                            Cb[off] = __float2bfloat16_rn(v0);
                            Cb[off + 1] = __float2bfloat16_rn(v1);
                        }
                    }
                } else if (gc < N) {
                    C[off] = v0;
                    if (Cb) Cb[off] = __float2bfloat16_rn(v0);
                }
            }
        }
    }
}

// ==================== SIMT GEMM (zbase only) ====================
template <int BM, int BN, int BK, int TM, int TN>
__global__ void gemm_nt(const float* __restrict__ A, int lda,
                        const float* __restrict__ Bm, int ldb,
                        float* __restrict__ C, int ldc,
                        int M, int N, int K,
                        long long sA, long long sB, long long sC)
{
    constexpr int THREADS = (BM / TM) * (BN / TN);
    __shared__ float As[BK][BM + 4];
    __shared__ float Bs[BK][BN + 4];

    A += (long long)blockIdx.z * sA;
    Bm += (long long)blockIdx.z * sB;
    C += (long long)blockIdx.z * sC;

    const int tid = threadIdx.x;
    const int bm0 = blockIdx.y * BM;
    const int bn0 = blockIdx.x * BN;
    const int tm = (tid / (BN / TN)) * TM;
    const int tn = (tid % (BN / TN)) * TN;

    float acc[TM][TN];
#pragma unroll
    for (int i = 0; i < TM; i++)
#pragma unroll
        for (int j = 0; j < TN; j++) acc[i][j] = 0.f;

    for (int k0 = 0; k0 < K; k0 += BK) {
#pragma unroll
        for (int i = tid; i < BM * (BK / 4); i += THREADS) {
            int row = i / (BK / 4);
            int kc = i % (BK / 4);
            int gm = bm0 + row;
            int gk = k0 + kc * 4;
            float4 v = make_float4(0.f, 0.f, 0.f, 0.f);
            if (gm < M) v = *reinterpret_cast<const float4*>(A + (size_t)gm * lda + gk);
            As[kc * 4 + 0][row] = v.x; As[kc * 4 + 1][row] = v.y;
            As[kc * 4 + 2][row] = v.z; As[kc * 4 + 3][row] = v.w;
        }
#pragma unroll
        for (int i = tid; i < BN * (BK / 4); i += THREADS) {
            int row = i / (BK / 4);
            int kc = i % (BK / 4);
            int gn = bn0 + row;
            int gk = k0 + kc * 4;
            float4 v = make_float4(0.f, 0.f, 0.f, 0.f);
            if (gn < N) v = *reinterpret_cast<const float4*>(Bm + (size_t)gn * ldb + gk);
            Bs[kc * 4 + 0][row] = v.x; Bs[kc * 4 + 1][row] = v.y;
            Bs[kc * 4 + 2][row] = v.z; Bs[kc * 4 + 3][row] = v.w;
        }
        __syncthreads();
#pragma unroll
        for (int k = 0; k < BK; k++) {
            float ra[TM], rb[TN];
#pragma unroll
            for (int i = 0; i < TM; i++) ra[i] = As[k][tm + i];
#pragma unroll
            for (int j = 0; j < TN; j++) rb[j] = Bs[k][tn + j];
#pragma unroll
            for (int i = 0; i < TM; i++)
#pragma unroll
                for (int j = 0; j < TN; j++) acc[i][j] += ra[i] * rb[j];
        }
        __syncthreads();
    }

#pragma unroll
    for (int i = 0; i < TM; i++) {
        int gm = bm0 + tm + i;
        if (gm >= M) continue;
#pragma unroll
        for (int j = 0; j < TN; j++) {
            int gn = bn0 + tn + j;
            if (gn >= N) continue;
            C[(size_t)gm * ldc + gn] = acc[i][j];
        }
    }
}

// ==================== small kernels ====================
#define NSEG 12
struct ConvSegs {
    const float* src[NSEG];
    bf16* dst[NSEG];
    int n4[NSEG];
};

__global__ void f2bf_multi(ConvSegs segs, int total4)
{
    int i = blockIdx.x * blockDim.x + threadIdx.x;
    if (i >= total4) return;
    int idx = i;
#pragma unroll
    for (int s = 0; s < NSEG; s++) {
        if (idx < segs.n4[s]) {
            float4 v = reinterpret_cast<const float4*>(segs.src[s])[idx];
            bf162* o = reinterpret_cast<bf162*>(segs.dst[s]) + idx * 2;
            o[0] = __floats2bfloat162_rn(v.x, v.y);
            o[1] = __floats2bfloat162_rn(v.z, v.w);
            return;
        }
        idx -= segs.n4[s];
    }
}

__global__ void mean_kernel(const float* __restrict__ x, bf16* __restrict__ mean_bf)
{
    int idx = blockIdx.x * blockDim.x + threadIdx.x;
    if (idx >= BB * CC) return;
    int b = idx / CC, c = idx % CC;
    float acc = 0.f;
    const float* p = x + (size_t)b * NN * CC + c;
#pragma unroll 7
    for (int n = 0; n < NN; n++) acc += p[(size_t)n * CC];
    mean_bf[idx] = __float2bfloat16_rn(acc * (1.f / (float)NN));
}

__global__ void cat_w3(const float* __restrict__ Wb, const float* __restrict__ Whi,
                       const float* __restrict__ Wmi, bf16* __restrict__ Wcat)
{
    int idx = blockIdx.x * blockDim.x + threadIdx.x;
    if (idx >= 3 * DD * CC) return;
    int r = idx / CC;
    const float* src = (r < DD) ? Wb : (r < 2 * DD) ? Whi : Wmi;
    int rr = (r < DD) ? r : (r < 2 * DD) ? r - DD : r - 2 * DD;
    Wcat[idx] = __float2bfloat16_rn(src[(size_t)rr * CC + (idx % CC)]);
}

__global__ void cat_bias3(const float* __restrict__ bb, const float* __restrict__ bhi,
                          const float* __restrict__ bmi, float* __restrict__ bcat,
                          const float* __restrict__ bih, const float* __restrict__ bhh,
                          float* __restrict__ bsum)
{
    int i = blockIdx.x * blockDim.x + threadIdx.x;
    if (i < 3 * DD)
        bcat[i] = (i < DD) ? bb[i] : (i < 2 * DD) ? bhi[i - DD] : bmi[i - 2 * DD];
    if (i < 4 * DD)
        bsum[i] = bih[i] + bhh[i];
}

__global__ void split_init(float* __restrict__ vg, bf16* __restrict__ h0,
                           float* __restrict__ m0)
{
    int idx = blockIdx.x * blockDim.x + threadIdx.x;
    if (idx >= BB * DD) return;
    int b = idx >> 9, d = idx & (DD - 1);
    const float* row = g_init + (size_t)b * (3 * DD);
    vg[idx] = row[d];
    h0[idx] = __float2bfloat16_rn(row[DD + d]);
    m0[idx] = row[2 * DD + d];
}

__global__ void xcat_build(const int* __restrict__ target, const float* __restrict__ emb)
{
    int idx = blockIdx.x * blockDim.x + threadIdx.x;
    if (idx >= RR * (DD + EE)) return;
    int c = idx & 1023;
    int r = idx >> 10;
    int b = r % BB, t = r / BB;
    float v;
    if (c < DD) {
        v = g_vg[(size_t)b * DD + c];
    } else {
        v = 0.f;
        if (t > 0) v = emb[(size_t)target[b * TT + (t - 1)] * EE + (c - DD)];
    }
    g_xcat_bf[idx] = __float2bfloat16_rn(v);
}

__global__ void lstm_elem(const float* __restrict__ xg_t,
                          float* __restrict__ m,
                          bf16* __restrict__ h_out,
                          float* __restrict__ tm_out)
{
    int idx = blockIdx.x * blockDim.x + threadIdx.x;
    if (idx >= BB * DD) return;
    int b = idx >> 9, d = idx & (DD - 1);
    const float* gr = g_gates + (size_t)b * (4 * DD);
    const float* xr = xg_t + (size_t)b * (4 * DD);
    float gi = gr[d] + xr[d];
    float gf = gr[DD + d] + xr[DD + d];
    float gg = gr[2 * DD + d] + xr[2 * DD + d];
    float go = gr[3 * DD + d] + xr[3 * DD + d];
    float m2 = sigmoidf_(gf) * m[idx] + sigmoidf_(gi) * tanhf(gg);
    float tm2 = tanhf(m2);
    m[idx] = m2;
    h_out[idx] = __float2bfloat16_rn(sigmoidf_(go) * tm2);
    tm_out[idx] = tm2;
}

__global__ void attn_batched(const float* __restrict__ wh, float* __restrict__ out_attn)
{
    int r = blockIdx.x;
    int t = r / BB, b = r % BB;
    int tid = threadIdx.x;
    __shared__ float gHs[NN], whs[NN], zs[NN + 1], alphas[NN + 1];
    if (tid < NN) { gHs[tid] = g_gH[(size_t)r * NN + tid]; whs[tid] = wh[tid]; }
    __syncthreads();

    if (tid < NN) {
        const float* zb = g_zbase + ((size_t)b * NN + tid) * NN;
        float acc = 0.f;
        for (int k = 0; k < NN; k++) acc += tanhf(zb[k] + gHs[k]) * whs[k];
        zs[tid] = acc;
    } else if (tid == NN) {
        const float* sw = g_sWs + (size_t)r * NN;
        float acc = 0.f;
        for (int k = 0; k < NN; k++) acc += tanhf(sw[k] + gHs[k]) * whs[k];
        zs[NN] = acc;
    }
    __syncthreads();

    if (tid == 0) {
        float mx = -1e30f;
        for (int i = 0; i <= NN; i++) mx = fmaxf(mx, zs[i]);
        float sum = 0.f;
        for (int i = 0; i <= NN; i++) { float e = expf(zs[i] - mx); alphas[i] = e; sum += e; }
        float inv = 1.f / sum;
        for (int i = 0; i <= NN; i++) alphas[i] *= inv;
    }
    __syncthreads();

    if (tid < NN) out_attn[((size_t)b * TT + t) * NN + tid] = alphas[tid];

    {
        int d = tid * 2;
        float aN = alphas[NN];
        float cx = aN * g_s[(size_t)r * DD + d];
        float cy = aN * g_s[(size_t)r * DD + d + 1];
        const bf162* vf = reinterpret_cast<const bf162*>(g_Vfb + (size_t)b * NN * DD + d);
#pragma unroll 7
        for (int n = 0; n < NN; n++) {
            float2 v = __bfloat1622float2(vf[n * (DD / 2)]);
            cx += alphas[n] * v.x;
            cy += alphas[n] * v.y;
        }
        cx += g_H[(size_t)r * DD + d];
        cy += g_H[(size_t)r * DD + d + 1];
        reinterpret_cast<bf162*>(g_ctxH_bf + (size_t)r * DD + d)[0] =
            __floats2bfloat162_rn(cx, cy);
    }
}

__global__ void logsoftmax_kernel(float* __restrict__ out)
{
    int r = blockIdx.x;
    int t = r / BB, b = r % BB;
    const float4* row = reinterpret_cast<const float4*>(g_logits + (size_t)r * VOC);
    const int NV = VOC / 4;
    __shared__ float red[512];
    float mx = -1e30f;
    for (int v = threadIdx.x; v < NV; v += 512) {
        float4 x = row[v];
        mx = fmaxf(mx, fmaxf(fmaxf(x.x, x.y), fmaxf(x.z, x.w)));
    }
    red[threadIdx.x] = mx; __syncthreads();
    for (int s = 256; s > 0; s >>= 1) {
        if (threadIdx.x < s) red[threadIdx.x] = fmaxf(red[threadIdx.x], red[threadIdx.x + s]);
        __syncthreads();
    }
    mx = red[0]; __syncthreads();
    float sum = 0.f;
    for (int v = threadIdx.x; v < NV; v += 512) {
        float4 x = row[v];
        sum += expf(x.x - mx) + expf(x.y - mx) + expf(x.z - mx) + expf(x.w - mx);
    }
    red[threadIdx.x] = sum; __syncthreads();
    for (int s = 256; s > 0; s >>= 1) {
        if (threadIdx.x < s) red[threadIdx.x] += red[threadIdx.x + s];
        __syncthreads();
    }
    float lse = mx + logf(red[0]);
    float4* orow = reinterpret_cast<float4*>(out + ((size_t)b * TT + t) * VOC);
    for (int v = threadIdx.x; v < NV; v += 512) {
        float4 x = row[v];
        orow[v] = make_float4(x.x - lse, x.y - lse, x.z - lse, x.w - lse);
    }
}

// ==================== host ====================
static inline void tc(const bf16* A, int lda, const bf16* B, int ldb,
                      const float* bias, float* C, bf16* Cb, int ldc,
                      int Mtiles, int N, int K, int act,
                      const float* aux1 = nullptr, const float* aux2 = nullptr)
{
    dim3 grid((N + 127) / 128, Mtiles);
    gemm_bf<<<grid, 256, SMEM_MM>>>(A, lda, B, ldb, bias, C, Cb, ldc, N, K, act, aux1, aux2);
}

static inline void tc64(const bf16* A, int lda, const bf16* B, int ldb,
                        const float* bias, float* C, bf16* Cb, int ldc,
                        int Mtiles, int N, int K, int act)
{
    dim3 grid((N + 63) / 64, Mtiles);
    gemm_bf64<<<grid, 256, SMEM_MM64>>>(A, lda, B, ldb, bias, C, Cb, ldc, N, K, act);
}

extern "C" void kernel_launch(void* const* d_in, const int* in_sizes, int n_in,
                              void* d_out, int out_size)
{
    const float* image = (const float*)d_in[0];
    const int*   target = (const int*)d_in[1];
    const float* emb = (const float*)d_in[2];
    const float* Wa = (const float*)d_in[3];  const float* ba = (const float*)d_in[4];
    const float* Wb = (const float*)d_in[5];  const float* bb = (const float*)d_in[6];
    const float* Whi = (const float*)d_in[7]; const float* bhi = (const float*)d_in[8];
    const float* Wmi = (const float*)d_in[9]; const float* bmi = (const float*)d_in[10];
    const float* Wih = (const float*)d_in[11]; const float* bih = (const float*)d_in[12];
    const float* Whh = (const float*)d_in[13]; const float* bhh = (const float*)d_in[14];
    const float* Wv = (const float*)d_in[15];
    const float* Wg = (const float*)d_in[16];
    const float* wh = (const float*)d_in[17];
    const float* WH = (const float*)d_in[18];
    const float* Wx = (const float*)d_in[19];
    const float* Wh2 = (const float*)d_in[20];
    const float* Ws = (const float*)d_in[21];
    const float* Wc = (const float*)d_in[22]; const float* bc = (const float*)d_in[23];
    const float* Wfc = (const float*)d_in[24]; const float* bfc = (const float*)d_in[25];
    const float* Wp = (const float*)d_in[26]; const float* bp = (const float*)d_in[27];

    float* out = (float*)d_out;
    float* out_attn = out + (size_t)BB * TT * VOC;

    static int attr_set = 0;
    if (!attr_set) {
        cudaFuncSetAttribute(gemm_bf, cudaFuncAttributeMaxDynamicSharedMemorySize, SMEM_MM);
        cudaFuncSetAttribute(gemm_bf64, cudaFuncAttributeMaxDynamicSharedMemorySize, SMEM_MM64);
        attr_set = 1;
    }

    float *p_Vf, *p_zbase, *p_bcat, *p_vg, *p_m, *p_tm, *p_bsum, *p_xg, *p_xx, *p_gates;
    float *p_H, *p_s, *p_gH, *p_sWs, *p_out, *p_logits, *p_init;
    bf16 *pb_image, *pb_Wa, *pb_mean, *pb_Wcat, *pb_xcat, *pb_Wih, *pb_Wx, *pb_Whh;
    bf16 *pb_Wh2, *pb_WH, *pb_Wc, *pb_Wfc, *pb_Wp, *pb_Wg, *pb_Ws;
    bf16 *pb_hseq, *pb_a, *pb_ctxH, *pb_out, *pb_Vfb, *pb_H, *pb_s;
    cudaGetSymbolAddress((void**)&p_Vf, g_Vf);
    cudaGetSymbolAddress((void**)&p_zbase, g_zbase);
    cudaGetSymbolAddress((void**)&p_bcat, g_bcat);
    cudaGetSymbolAddress((void**)&p_init, g_init);
    cudaGetSymbolAddress((void**)&p_vg, g_vg);
    cudaGetSymbolAddress((void**)&p_m, g_m);
    cudaGetSymbolAddress((void**)&p_tm, g_tm);
    cudaGetSymbolAddress((void**)&p_bsum, g_bsum);
    cudaGetSymbolAddress((void**)&p_xg, g_xg);
    cudaGetSymbolAddress((void**)&p_xx, g_xx);
    cudaGetSymbolAddress((void**)&p_gates, g_gates);
    cudaGetSymbolAddress((void**)&p_H, g_H);
    cudaGetSymbolAddress((void**)&p_s, g_s);
    cudaGetSymbolAddress((void**)&p_gH, g_gH);
    cudaGetSymbolAddress((void**)&p_sWs, g_sWs);
    cudaGetSymbolAddress((void**)&p_out, g_out);
    cudaGetSymbolAddress((void**)&p_logits, g_logits);
    cudaGetSymbolAddress((void**)&pb_image, g_image_bf);
    cudaGetSymbolAddress((void**)&pb_Wa, g_Wa_bf);
    cudaGetSymbolAddress((void**)&pb_mean, g_mean_bf);
    cudaGetSymbolAddress((void**)&pb_Wcat, g_Wcat_bf);
    cudaGetSymbolAddress((void**)&pb_xcat, g_xcat_bf);
    cudaGetSymbolAddress((void**)&pb_Wih, g_Wih_bf);
    cudaGetSymbolAddress((void**)&pb_Wx, g_Wx_bf);
    cudaGetSymbolAddress((void**)&pb_Whh, g_Whh_bf);
    cudaGetSymbolAddress((void**)&pb_Wh2, g_Wh2_bf);
    cudaGetSymbolAddress((void**)&pb_WH, g_WH_bf);
    cudaGetSymbolAddress((void**)&pb_Wc, g_Wc_bf);
    cudaGetSymbolAddress((void**)&pb_Wfc, g_Wfc_bf);
    cudaGetSymbolAddress((void**)&pb_Wp, g_Wp_bf);
    cudaGetSymbolAddress((void**)&pb_Wg, g_Wg_bf);
    cudaGetSymbolAddress((void**)&pb_Ws, g_Ws_bf);
    cudaGetSymbolAddress((void**)&pb_hseq, g_hseq_bf);
    cudaGetSymbolAddress((void**)&pb_a, g_a_bf);
    cudaGetSymbolAddress((void**)&pb_ctxH, g_ctxH_bf);
    cudaGetSymbolAddress((void**)&pb_out, g_out_bf);
    cudaGetSymbolAddress((void**)&pb_Vfb, g_Vfb);
    cudaGetSymbolAddress((void**)&pb_H, g_H_bf);
    cudaGetSymbolAddress((void**)&pb_s, g_s_bf);

    // ---- conversions (single launch) ----
    {
        ConvSegs segs;
        const float* srcs[NSEG] = { image, Wa, Wih, Wx, Whh, Wh2, WH, Wc, Wfc, Wp, Wg, Ws };
        bf16* dsts[NSEG] = { pb_image, pb_Wa, pb_Wih, pb_Wx, pb_Whh, pb_Wh2, pb_WH,
                             pb_Wc, pb_Wfc, pb_Wp, pb_Wg, pb_Ws };
        int ns[NSEG] = { BB * NN * CC / 4, DD * CC / 4, 4 * DD * (DD + EE) / 4,
                         DD * (DD + EE) / 4, 4 * DD * DD / 4, DD * DD / 4, DD * DD / 4,
                         DD * DD / 4, DD * DD / 4, VOC * DD / 4, NN * DD / 4, NN * DD / 4 };
        int total4 = 0;
        for (int i = 0; i < NSEG; i++) { segs.src[i] = srcs[i]; segs.dst[i] = dsts[i]; segs.n4[i] = ns[i]; total4 += ns[i]; }
        f2bf_multi<<<(total4 + 255) / 256, 256>>>(segs, total4);
    }
    cat_bias3<<<(4 * DD + 255) / 256, 256>>>(bb, bhi, bmi, p_bcat, bih, bhh, p_bsum);

    // ---- precompute ----
    mean_kernel<<<(BB * CC + 255) / 256, 256>>>(image, pb_mean);
    tc(pb_image, CC, pb_Wa, CC, ba, p_Vf, pb_Vfb, DD, BB * NN / 128, DD, CC, 1);
    cat_w3<<<(3 * DD * CC + 255) / 256, 256>>>(Wb, Whi, Wmi, pb_Wcat);
    tc(pb_mean, CC, pb_Wcat, CC, p_bcat, p_init, nullptr, 3 * DD, 1, 3 * DD, CC, 1);
    split_init<<<(BB * DD + 255) / 256, 256>>>(p_vg, pb_hseq, p_m);
    {
        dim3 grid(1, 1, BB);
        gemm_nt<64, 64, 16, 4, 4><<<grid, 256>>>(p_Vf, DD, Wv, DD, p_zbase, NN,
                                                 NN, NN, DD,
                                                 (long long)NN * DD, 0, (long long)NN * NN);
    }
    xcat_build<<<(RR * (DD + EE) + 255) / 256, 256>>>(target, emb);
    tc(pb_xcat, DD + EE, pb_Wih, DD + EE, p_bsum, p_xg, nullptr, 4 * DD, RR / 128, 4 * DD, DD + EE, 0);
    tc(pb_xcat, DD + EE, pb_Wx, DD + EE, nullptr, p_xx, nullptr, DD, RR / 128, DD, DD + EE, 0);

    // ---- sequential recurrence: gates GEMM (BN=64, 32 CTAs) + elementwise ----
    for (int t = 0; t < TT; t++) {
        tc64(pb_hseq + (size_t)t * BB * DD, DD, pb_Whh, DD, nullptr, p_gates, nullptr,
             4 * DD, 1, 4 * DD, DD, 0);
        lstm_elem<<<(BB * DD + 255) / 256, 256>>>(p_xg + (size_t)t * BB * 4 * DD,
                                                  p_m,
                                                  pb_hseq + (size_t)(t + 1) * BB * DD,
                                                  p_tm + (size_t)t * BB * DD);
    }

    // ---- batched epilogue over RR rows ----
    const bf16* Hp = pb_hseq;
    const bf16* Hc = pb_hseq + (size_t)BB * DD;
    tc(Hp, DD, pb_Wh2, DD, nullptr, nullptr, pb_a, DD, RR / 128, DD, DD, 3, p_xx, p_tm);
    tc(Hc, DD, pb_WH, DD, nullptr, p_H, pb_H, DD, RR / 128, DD, DD, 1);
    tc(pb_a, DD, pb_Wc, DD, bc, p_s, pb_s, DD, RR / 128, DD, DD, 1);
    tc64(pb_H, DD, pb_Wg, DD, nullptr, p_gH, nullptr, NN, RR / 128, NN, DD, 0);
    tc64(pb_s, DD, pb_Ws, DD, nullptr, p_sWs, nullptr, NN, RR / 128, NN, DD, 0);
    attn_batched<<<RR, 256>>>(wh, out_attn);
    tc(pb_ctxH, DD, pb_Wfc, DD, bfc, p_out, pb_out, DD, RR / 128, DD, DD, 2);

    // ---- logits + log_softmax ----
    tc(pb_out, DD, pb_Wp, DD, bp, p_logits, nullptr, VOC, RR / 128, VOC, DD, 0);
    logsoftmax_kernel<<<RR, 512>>>(out);
}

// round 14
// speedup vs baseline: 1.4275x; 1.0013x over previous
#include <cuda_runtime.h>
#include <cuda_bf16.h>
#include <math.h>
#include <stdint.h>

#define BB 128
#define NN 49
#define CC 2048
#define DD 512
#define EE 512
#define VOC 10000
#define TT 20
#define RR (TT * BB)

typedef __nv_bfloat16 bf16;
typedef __nv_bfloat162 bf162;

// ---------------- fp32 scratch ----------------
__device__ float g_Vf[BB * NN * DD];
__device__ float g_zbase[BB * NN * NN];
__device__ float g_bcat[3 * DD];
__device__ float g_init[BB * 3 * DD];
__device__ float g_vg[BB * DD];
__device__ float g_m[BB * DD];
__device__ float g_tm[RR * DD];
__device__ float g_bsum[4 * DD];
__device__ float g_xg[RR * 4 * DD];
__device__ float g_xx[RR * DD];
__device__ float g_gates[BB * 4 * DD];
__device__ float g_H[RR * DD];
__device__ float g_s[RR * DD];
__device__ float g_gH[RR * NN];
__device__ float g_sWs[RR * NN];
__device__ float g_out[RR * DD];
__device__ float g_logits[(size_t)RR * VOC];

// ---------------- bf16 scratch ----------------
__device__ __align__(16) bf16 g_image_bf[BB * NN * CC];
__device__ __align__(16) bf16 g_Wa_bf[DD * CC];
__device__ __align__(16) bf16 g_mean_bf[BB * CC];
__device__ __align__(16) bf16 g_Wcat_bf[3 * DD * CC];
__device__ __align__(16) bf16 g_xcat_bf[RR * (DD + EE)];
__device__ __align__(16) bf16 g_Wih_bf[4 * DD * (DD + EE)];
__device__ __align__(16) bf16 g_Wx_bf[DD * (DD + EE)];
__device__ __align__(16) bf16 g_Whh_bf[4 * DD * DD];
__device__ __align__(16) bf16 g_Wh2_bf[DD * DD];
__device__ __align__(16) bf16 g_WH_bf[DD * DD];
__device__ __align__(16) bf16 g_Wc_bf[DD * DD];
__device__ __align__(16) bf16 g_Wfc_bf[DD * DD];
__device__ __align__(16) bf16 g_Wp_bf[VOC * DD];
__device__ __align__(16) bf16 g_Wg_bf[NN * DD];
__device__ __align__(16) bf16 g_Ws_bf[NN * DD];
__device__ __align__(16) bf16 g_hseq_bf[(TT + 1) * BB * DD];
__device__ __align__(16) bf16 g_a_bf[RR * DD];
__device__ __align__(16) bf16 g_ctxH_bf[RR * DD];
__device__ __align__(16) bf16 g_out_bf[RR * DD];
__device__ __align__(16) bf16 g_Vfb[BB * NN * DD];
__device__ __align__(16) bf16 g_H_bf[RR * DD];
__device__ __align__(16) bf16 g_s_bf[RR * DD];

__device__ __forceinline__ float sigmoidf_(float x) { return 1.f / (1.f + expf(-x)); }

__device__ __forceinline__ uint32_t smem_u32(const void* p) {
    uint32_t a;
    asm("{ .reg .u64 t; cvta.to.shared.u64 t, %1; cvt.u32.u64 %0, t; }" : "=r"(a) : "l"(p));
    return a;
}

__device__ __forceinline__ void cp_async16(uint32_t dst, const void* src, bool pred) {
    int sz = pred ? 16 : 0;
    asm volatile("cp.async.cg.shared.global [%0], [%1], 16, %2;"
                 :: "r"(dst), "l"(src), "r"(sz) : "memory");
}
#define CP_COMMIT() asm volatile("cp.async.commit_group;" ::: "memory")
#define CP_WAIT1()  asm volatile("cp.async.wait_group 1;" ::: "memory")

__device__ __forceinline__ void mma_bf16(float* c, const uint32_t* a, uint32_t b0, uint32_t b1)
{
    asm volatile(
        "mma.sync.aligned.m16n8k16.row.col.f32.bf16.bf16.f32 "
        "{%0,%1,%2,%3}, {%4,%5,%6,%7}, {%8,%9}, {%0,%1,%2,%3};"
        : "+f"(c[0]), "+f"(c[1]), "+f"(c[2]), "+f"(c[3])
        : "r"(a[0]), "r"(a[1]), "r"(a[2]), "r"(a[3]), "r"(b0), "r"(b1));
}

#define LDSM_X4(r0, r1, r2, r3, addr) \
    asm volatile("ldmatrix.sync.aligned.m8n8.x4.shared.b16 {%0,%1,%2,%3}, [%4];" \
        : "=r"(r0), "=r"(r1), "=r"(r2), "=r"(r3) : "r"(addr))

// BK=64 tiling: row stride 72 bf16 (144 B = 9*16, aligned; ldmatrix bank-clean)
#define ASTR 72
#define ABUF (128 * ASTR)
#define BBUF64 (64 * ASTR)
#define SMEM_MM (4 * ABUF * 2)                  // 73728 B
#define SMEM_MM64 ((2 * ABUF + 2 * BBUF64) * 2) // 55296 B

// ==================== generic bf16 HMMA GEMM (BN=128, BK=64, ldmatrix) ====================
// act: 0 none, 1 relu, 2 tanh, 3: Cb = bf16( sigmoid(aux1+v)*aux2 ) only.
__global__ void __launch_bounds__(256, 2) gemm_bf(
    const bf16* __restrict__ A, int lda,
    const bf16* __restrict__ B, int ldb,
    const float* __restrict__ bias,
    float* __restrict__ C, bf16* __restrict__ Cb, int ldc,
    int N, int K, int act,
    const float* __restrict__ aux1, const float* __restrict__ aux2)
{
    extern __shared__ bf16 sm[];
    const uint32_t sA_u[2] = { smem_u32(sm), smem_u32(sm + ABUF) };
    const uint32_t sB_u[2] = { smem_u32(sm + 2 * ABUF), smem_u32(sm + 3 * ABUF) };

    const int tid = threadIdx.x;
    const int wid = tid >> 5, lane = tid & 31;
    const int g = lane >> 2, tg = lane & 3;
    const int wm = (wid & 3) * 32;
    const int wn = (wid >> 2) * 64;
    const int m0 = blockIdx.y * 128;
    const int n0 = blockIdx.x * 128;

    A += (size_t)m0 * lda;

    float acc[2][8][4];
#pragma unroll
    for (int mi = 0; mi < 2; mi++)
#pragma unroll
        for (int ni = 0; ni < 8; ni++)
#pragma unroll
            for (int q = 0; q < 4; q++) acc[mi][ni][q] = 0.f;

    const int KI = K >> 6;

    const int lm_q = lane >> 3;
    const int lm_r = lane & 7;
    const int a_row = wm + (lm_q & 1) * 8 + lm_r;
    const int a_col = (lm_q >> 1) * 8;
    const int b_row = (lm_q >> 1) * 8 + lm_r;
    const int b_col = (lm_q & 1) * 8;

    {
#pragma unroll
        for (int j = 0; j < 4; j++) {
            int pos = tid + j * 256;
            int row = pos >> 3, c8 = pos & 7;
            cp_async16(sA_u[0] + (row * ASTR + c8 * 8) * 2,
                       A + (size_t)row * lda + c8 * 8, true);
        }
#pragma unroll
        for (int j = 0; j < 4; j++) {
            int pos = tid + j * 256;
            int row = pos >> 3, c8 = pos & 7;
            int gn = n0 + row;
            bool ok = gn < N;
            int gs = ok ? gn : (N - 1);
            cp_async16(sB_u[0] + (row * ASTR + c8 * 8) * 2,
                       B + (size_t)gs * ldb + c8 * 8, ok);
        }
        CP_COMMIT();
    }

    for (int i = 0; i < KI; i++) {
        const int cur = i & 1;
        if (i + 1 < KI) {
            const int nxt = cur ^ 1;
            const int k0 = (i + 1) << 6;
#pragma unroll
            for (int j = 0; j < 4; j++) {
                int pos = tid + j * 256;
                int row = pos >> 3, c8 = pos & 7;
                cp_async16(sA_u[nxt] + (row * ASTR + c8 * 8) * 2,
                           A + (size_t)row * lda + k0 + c8 * 8, true);
            }
#pragma unroll
            for (int j = 0; j < 4; j++) {
                int pos = tid + j * 256;
                int row = pos >> 3, c8 = pos & 7;
                int gn = n0 + row;
                bool ok = gn < N;
                int gs = ok ? gn : (N - 1);
                cp_async16(sB_u[nxt] + (row * ASTR + c8 * 8) * 2,
                           B + (size_t)gs * ldb + k0 + c8 * 8, ok);
            }
        }
        CP_COMMIT();
        CP_WAIT1();
        __syncthreads();

        const uint32_t sa = sA_u[cur];
        const uint32_t sb = sB_u[cur];
#pragma unroll
        for (int kk = 0; kk < 4; kk++) {
            const int kb = kk * 16;
            uint32_t a[2][4];
#pragma unroll
            for (int mi = 0; mi < 2; mi++) {
                uint32_t addr = sa + (((a_row + mi * 16) * ASTR) + kb + a_col) * 2;
                LDSM_X4(a[mi][0], a[mi][1], a[mi][2], a[mi][3], addr);
            }
#pragma unroll
            for (int nip = 0; nip < 4; nip++) {
                uint32_t b0, b1, b2, b3;
                uint32_t addr = sb + (((wn + nip * 16 + b_row) * ASTR) + kb + b_col) * 2;
                LDSM_X4(b0, b1, b2, b3, addr);
                mma_bf16(acc[0][2 * nip], a[0], b0, b1);
                mma_bf16(acc[1][2 * nip], a[1], b0, b1);
                mma_bf16(acc[0][2 * nip + 1], a[0], b2, b3);
                mma_bf16(acc[1][2 * nip + 1], a[1], b2, b3);
            }
        }
        __syncthreads();
    }

#pragma unroll
    for (int mi = 0; mi < 2; mi++) {
#pragma unroll
        for (int ni = 0; ni < 8; ni++) {
            int gr = m0 + wm + mi * 16 + g;
            int gc = n0 + wn + ni * 8 + 2 * tg;
#pragma unroll
            for (int qr = 0; qr < 2; qr++) {
                int r = gr + qr * 8;
                float v0 = acc[mi][ni][qr * 2 + 0];
                float v1 = acc[mi][ni][qr * 2 + 1];
                size_t off = (size_t)r * ldc + gc;
                bool aligned = ((off & 1) == 0);
                if (act == 3) {
                    if (gc + 1 < N) {
                        float a0 = sigmoidf_(aux1[off] + v0) * aux2[off];
                        float a1 = sigmoidf_(aux1[off + 1] + v1) * aux2[off + 1];
                        if (aligned) {
                            *reinterpret_cast<bf162*>(Cb + off) = __floats2bfloat162_rn(a0, a1);
                        } else {
                            Cb[off] = __float2bfloat16_rn(a0);
                            Cb[off + 1] = __float2bfloat16_rn(a1);
                        }
                    } else if (gc < N) {
                        Cb[off] = __float2bfloat16_rn(sigmoidf_(aux1[off] + v0) * aux2[off]);
                    }
                } else {
                    if (bias) { v0 += bias[gc]; if (gc + 1 < N) v1 += bias[gc + 1]; }
                    if (act == 1) { v0 = fmaxf(v0, 0.f); v1 = fmaxf(v1, 0.f); }
                    else if (act == 2) { v0 = tanhf(v0); v1 = tanhf(v1); }
                    if (gc + 1 < N) {
                        if (aligned) {
                            *reinterpret_cast<float2*>(C + off) = make_float2(v0, v1);
                            if (Cb) *reinterpret_cast<bf162*>(Cb + off) = __floats2bfloat162_rn(v0, v1);
                        } else {
                            C[off] = v0; C[off + 1] = v1;
                            if (Cb) {
                                Cb[off] = __float2bfloat16_rn(v0);
                                Cb[off + 1] = __float2bfloat16_rn(v1);
                            }
                        }
                    } else if (gc < N) {
                        C[off] = v0;
                        if (Cb) Cb[off] = __float2bfloat16_rn(v0);
                    }
                }
            }
        }
    }
}

// ==================== BN=64, BK=64 bf16 HMMA GEMM (ldmatrix) ====================
__global__ void __launch_bounds__(256, 2) gemm_bf64(
    const bf16* __restrict__ A, int lda,
    const bf16* __restrict__ B, int ldb,
    const float* __restrict__ bias,
    float* __restrict__ C, bf16* __restrict__ Cb, int ldc,
    int N, int K, int act)
{
    extern __shared__ bf16 sm[];
    const uint32_t sA_u[2] = { smem_u32(sm), smem_u32(sm + ABUF) };
    const uint32_t sB_u[2] = { smem_u32(sm + 2 * ABUF), smem_u32(sm + 2 * ABUF + BBUF64) };

    const int tid = threadIdx.x;
    const int wid = tid >> 5, lane = tid & 31;
    const int g = lane >> 2, tg = lane & 3;
    const int wm = (wid & 3) * 32;
    const int wn = (wid >> 2) * 32;
    const int m0 = blockIdx.y * 128;
    const int n0 = blockIdx.x * 64;

    A += (size_t)m0 * lda;

    float acc[2][4][4];
#pragma unroll
    for (int mi = 0; mi < 2; mi++)
#pragma unroll
        for (int ni = 0; ni < 4; ni++)
#pragma unroll
            for (int q = 0; q < 4; q++) acc[mi][ni][q] = 0.f;

    const int KI = K >> 6;

    const int lm_q = lane >> 3;
    const int lm_r = lane & 7;
    const int a_row = wm + (lm_q & 1) * 8 + lm_r;
    const int a_col = (lm_q >> 1) * 8;
    const int b_row = (lm_q >> 1) * 8 + lm_r;
    const int b_col = (lm_q & 1) * 8;

    {
#pragma unroll
        for (int j = 0; j < 4; j++) {
            int pos = tid + j * 256;
            int row = pos >> 3, c8 = pos & 7;
            cp_async16(sA_u[0] + (row * ASTR + c8 * 8) * 2,
                       A + (size_t)row * lda + c8 * 8, true);
        }
#pragma unroll
        for (int j = 0; j < 2; j++) {
            int pos = tid + j * 256;
            int row = pos >> 3, c8 = pos & 7;
            int gn = n0 + row;
            bool ok = gn < N;
            int gs = ok ? gn : (N - 1);
            cp_async16(sB_u[0] + (row * ASTR + c8 * 8) * 2,
                       B + (size_t)gs * ldb + c8 * 8, ok);
        }
        CP_COMMIT();
    }

    for (int i = 0; i < KI; i++) {
        const int cur = i & 1;
        if (i + 1 < KI) {
            const int nxt = cur ^ 1;
            const int k0 = (i + 1) << 6;
#pragma unroll
            for (int j = 0; j < 4; j++) {
                int pos = tid + j * 256;
                int row = pos >> 3, c8 = pos & 7;
                cp_async16(sA_u[nxt] + (row * ASTR + c8 * 8) * 2,
                           A + (size_t)row * lda + k0 + c8 * 8, true);
            }
#pragma unroll
            for (int j = 0; j < 2; j++) {
                int pos = tid + j * 256;
                int row = pos >> 3, c8 = pos & 7;
                int gn = n0 + row;
                bool ok = gn < N;
                int gs = ok ? gn : (N - 1);
                cp_async16(sB_u[nxt] + (row * ASTR + c8 * 8) * 2,
                           B + (size_t)gs * ldb + k0 + c8 * 8, ok);
            }
        }
        CP_COMMIT();
        CP_WAIT1();
        __syncthreads();

        const uint32_t sa = sA_u[cur];
        const uint32_t sb = sB_u[cur];
#pragma unroll
        for (int kk = 0; kk < 4; kk++) {
            const int kb = kk * 16;
            uint32_t a[2][4];
#pragma unroll
            for (int mi = 0; mi < 2; mi++) {
                uint32_t addr = sa + (((a_row + mi * 16) * ASTR) + kb + a_col) * 2;
                LDSM_X4(a[mi][0], a[mi][1], a[mi][2], a[mi][3], addr);
            }
#pragma unroll
            for (int nip = 0; nip < 2; nip++) {
                uint32_t b0, b1, b2, b3;
                uint32_t addr = sb + (((wn + nip * 16 + b_row) * ASTR) + kb + b_col) * 2;
                LDSM_X4(b0, b1, b2, b3, addr);
                mma_bf16(acc[0][2 * nip], a[0], b0, b1);
                mma_bf16(acc[1][2 * nip], a[1], b0, b1);
                mma_bf16(acc[0][2 * nip + 1], a[0], b2, b3);
                mma_bf16(acc[1][2 * nip + 1], a[1], b2, b3);
            }
        }
        __syncthreads();
    }

#pragma unroll
    for (int mi = 0; mi < 2; mi++) {
#pragma unroll
        for (int ni = 0; ni < 4; ni++) {
            int gr = m0 + wm + mi * 16 + g;
            int gc = n0 + wn + ni * 8 + 2 * tg;
#pragma unroll
            for (int qr = 0; qr < 2; qr++) {
                int r = gr + qr * 8;
                float v0 = acc[mi][ni][qr * 2 + 0];
                float v1 = acc[mi][ni][qr * 2 + 1];
                size_t off = (size_t)r * ldc + gc;
                bool aligned = ((off & 1) == 0);
                if (bias) { v0 += bias[gc]; if (gc + 1 < N) v1 += bias[gc + 1]; }
                if (act == 1) { v0 = fmaxf(v0, 0.f); v1 = fmaxf(v1, 0.f); }
                else if (act == 2) { v0 = tanhf(v0); v1 = tanhf(v1); }
                if (gc + 1 < N) {
                    if (aligned) {
                        *reinterpret_cast<float2*>(C + off) = make_float2(v0, v1);
                        if (Cb) *reinterpret_cast<bf162*>(Cb + off) = __floats2bfloat162_rn(v0, v1);
                    } else {
                        C[off] = v0; C[off + 1] = v1;
                        if (Cb) {
                            Cb[off] = __float2bfloat16_rn(v0);
                            Cb[off + 1] = __float2bfloat16_rn(v1);
                        }
                    }
                } else if (gc < N) {
                    C[off] = v0;
                    if (Cb) Cb[off] = __float2bfloat16_rn(v0);
                }
            }
        }
    }
}

// ==================== SIMT GEMM (zbase only) ====================
template <int BM, int BN, int BK, int TM, int TN>
__global__ void gemm_nt(const float* __restrict__ A, int lda,
                        const float* __restrict__ Bm, int ldb,
                        float* __restrict__ C, int ldc,
                        int M, int N, int K,
                        long long sA, long long sB, long long sC)
{
    constexpr int THREADS = (BM / TM) * (BN / TN);
    __shared__ float As[BK][BM + 4];
    __shared__ float Bs[BK][BN + 4];

    A += (long long)blockIdx.z * sA;
    Bm += (long long)blockIdx.z * sB;
    C += (long long)blockIdx.z * sC;

    const int tid = threadIdx.x;
    const int bm0 = blockIdx.y * BM;
    const int bn0 = blockIdx.x * BN;
    const int tm = (tid / (BN / TN)) * TM;
    const int tn = (tid % (BN / TN)) * TN;

    float acc[TM][TN];
#pragma unroll
    for (int i = 0; i < TM; i++)
#pragma unroll
        for (int j = 0; j < TN; j++) acc[i][j] = 0.f;

    for (int k0 = 0; k0 < K; k0 += BK) {
#pragma unroll
        for (int i = tid; i < BM * (BK / 4); i += THREADS) {
            int row = i / (BK / 4);
            int kc = i % (BK / 4);
            int gm = bm0 + row;
            int gk = k0 + kc * 4;
            float4 v = make_float4(0.f, 0.f, 0.f, 0.f);
            if (gm < M) v = *reinterpret_cast<const float4*>(A + (size_t)gm * lda + gk);
            As[kc * 4 + 0][row] = v.x; As[kc * 4 + 1][row] = v.y;
            As[kc * 4 + 2][row] = v.z; As[kc * 4 + 3][row] = v.w;
        }
#pragma unroll
        for (int i = tid; i < BN * (BK / 4); i += THREADS) {
            int row = i / (BK / 4);
            int kc = i % (BK / 4);
            int gn = bn0 + row;
            int gk = k0 + kc * 4;
            float4 v = make_float4(0.f, 0.f, 0.f, 0.f);
            if (gn < N) v = *reinterpret_cast<const float4*>(Bm + (size_t)gn * ldb + gk);
            Bs[kc * 4 + 0][row] = v.x; Bs[kc * 4 + 1][row] = v.y;
            Bs[kc * 4 + 2][row] = v.z; Bs[kc * 4 + 3][row] = v.w;
        }
        __syncthreads();
#pragma unroll
        for (int k = 0; k < BK; k++) {
            float ra[TM], rb[TN];
#pragma unroll
            for (int i = 0; i < TM; i++) ra[i] = As[k][tm + i];
#pragma unroll
            for (int j = 0; j < TN; j++) rb[j] = Bs[k][tn + j];
#pragma unroll
            for (int i = 0; i < TM; i++)
#pragma unroll
                for (int j = 0; j < TN; j++) acc[i][j] += ra[i] * rb[j];
        }
        __syncthreads();
    }

#pragma unroll
    for (int i = 0; i < TM; i++) {
        int gm = bm0 + tm + i;
        if (gm >= M) continue;
#pragma unroll
        for (int j = 0; j < TN; j++) {
            int gn = bn0 + tn + j;
            if (gn >= N) continue;
            C[(size_t)gm * ldc + gn] = acc[i][j];
        }
    }
}

// ==================== small kernels ====================
#define NSEG 12
struct ConvSegs {
    const float* src[NSEG];
    bf16* dst[NSEG];
    int n4[NSEG];
};

__global__ void f2bf_multi(ConvSegs segs, int total4)
{
    int i = blockIdx.x * blockDim.x + threadIdx.x;
    if (i >= total4) return;
    int idx = i;
#pragma unroll
    for (int s = 0; s < NSEG; s++) {
        if (idx < segs.n4[s]) {
            float4 v = reinterpret_cast<const float4*>(segs.src[s])[idx];
            bf162* o = reinterpret_cast<bf162*>(segs.dst[s]) + idx * 2;
            o[0] = __floats2bfloat162_rn(v.x, v.y);
            o[1] = __floats2bfloat162_rn(v.z, v.w);
            return;
        }
        idx -= segs.n4[s];
    }
}

__global__ void mean_kernel(const float* __restrict__ x, bf16* __restrict__ mean_bf)
{
    int idx = blockIdx.x * blockDim.x + threadIdx.x;
    if (idx >= BB * CC) return;
    int b = idx / CC, c = idx % CC;
    float acc = 0.f;
    const float* p = x + (size_t)b * NN * CC + c;
#pragma unroll 7
    for (int n = 0; n < NN; n++) acc += p[(size_t)n * CC];
    mean_bf[idx] = __float2bfloat16_rn(acc * (1.f / (float)NN));
}

__global__ void cat_w3(const float* __restrict__ Wb, const float* __restrict__ Whi,
                       const float* __restrict__ Wmi, bf16* __restrict__ Wcat)
{
    int idx = blockIdx.x * blockDim.x + threadIdx.x;
    if (idx >= 3 * DD * CC) return;
    int r = idx / CC;
    const float* src = (r < DD) ? Wb : (r < 2 * DD) ? Whi : Wmi;
    int rr = (r < DD) ? r : (r < 2 * DD) ? r - DD : r - 2 * DD;
    Wcat[idx] = __float2bfloat16_rn(src[(size_t)rr * CC + (idx % CC)]);
}

__global__ void cat_bias3(const float* __restrict__ bb, const float* __restrict__ bhi,
                          const float* __restrict__ bmi, float* __restrict__ bcat,
                          const float* __restrict__ bih, const float* __restrict__ bhh,
                          float* __restrict__ bsum)
{
    int i = blockIdx.x * blockDim.x + threadIdx.x;
    if (i < 3 * DD)
        bcat[i] = (i < DD) ? bb[i] : (i < 2 * DD) ? bhi[i - DD] : bmi[i - 2 * DD];
    if (i < 4 * DD)
        bsum[i] = bih[i] + bhh[i];
}

__global__ void split_init(float* __restrict__ vg, bf16* __restrict__ h0,
                           float* __restrict__ m0)
{
    int idx = blockIdx.x * blockDim.x + threadIdx.x;
    if (idx >= BB * DD) return;
    int b = idx >> 9, d = idx & (DD - 1);
    const float* row = g_init + (size_t)b * (3 * DD);
    vg[idx] = row[d];
    h0[idx] = __float2bfloat16_rn(row[DD + d]);
    m0[idx] = row[2 * DD + d];
}

__global__ void xcat_build(const int* __restrict__ target, const float* __restrict__ emb)
{
    int idx = blockIdx.x * blockDim.x + threadIdx.x;
    if (idx >= RR * (DD + EE)) return;
    int c = idx & 1023;
    int r = idx >> 10;
    int b = r % BB, t = r / BB;
    float v;
    if (c < DD) {
        v = g_vg[(size_t)b * DD + c];
    } else {
        v = 0.f;
        if (t > 0) v = emb[(size_t)target[b * TT + (t - 1)] * EE + (c - DD)];
    }
    g_xcat_bf[idx] = __float2bfloat16_rn(v);
}

__global__ void lstm_elem(const float* __restrict__ xg_t,
                          float* __restrict__ m,
                          bf16* __restrict__ h_out,
                          float* __restrict__ tm_out)
{
    int idx = blockIdx.x * blockDim.x + threadIdx.x;
    if (idx >= BB * DD) return;
    int b = idx >> 9, d = idx & (DD - 1);
    const float* gr = g_gates + (size_t)b * (4 * DD);
    const float* xr = xg_t + (size_t)b * (4 * DD);
    float gi = gr[d] + xr[d];
    float gf = gr[DD + d] + xr[DD + d];
    float gg = gr[2 * DD + d] + xr[2 * DD + d];
    float go = gr[3 * DD + d] + xr[3 * DD + d];
    float m2 = sigmoidf_(gf) * m[idx] + sigmoidf_(gi) * tanhf(gg);
    float tm2 = tanhf(m2);
    m[idx] = m2;
    h_out[idx] = __float2bfloat16_rn(sigmoidf_(go) * tm2);
    tm_out[idx] = tm2;
}

__global__ void attn_batched(const float* __restrict__ wh, float* __restrict__ out_attn)
{
    int r = blockIdx.x;
    int t = r / BB, b = r % BB;
    int tid = threadIdx.x;
    __shared__ float gHs[NN], whs[NN], zs[NN + 1], alphas[NN + 1];
    if (tid < NN) { gHs[tid] = g_gH[(size_t)r * NN + tid]; whs[tid] = wh[tid]; }
    __syncthreads();

    if (tid < NN) {
        const float* zb = g_zbase + ((size_t)b * NN + tid) * NN;
        float acc = 0.f;
        for (int k = 0; k < NN; k++) acc += tanhf(zb[k] + gHs[k]) * whs[k];
        zs[tid] = acc;
    } else if (tid == NN) {
        const float* sw = g_sWs + (size_t)r * NN;
        float acc = 0.f;
        for (int k = 0; k < NN; k++) acc += tanhf(sw[k] + gHs[k]) * whs[k];
        zs[NN] = acc;
    }
    __syncthreads();

    if (tid == 0) {
        float mx = -1e30f;
        for (int i = 0; i <= NN; i++) mx = fmaxf(mx, zs[i]);
        float sum = 0.f;
        for (int i = 0; i <= NN; i++) { float e = expf(zs[i] - mx); alphas[i] = e; sum += e; }
        float inv = 1.f / sum;
        for (int i = 0; i <= NN; i++) alphas[i] *= inv;
    }
    __syncthreads();

    if (tid < NN) out_attn[((size_t)b * TT + t) * NN + tid] = alphas[tid];

    {
        int d = tid * 2;
        float aN = alphas[NN];
        float cx = aN * g_s[(size_t)r * DD + d];
        float cy = aN * g_s[(size_t)r * DD + d + 1];
        const bf162* vf = reinterpret_cast<const bf162*>(g_Vfb + (size_t)b * NN * DD + d);
#pragma unroll 7
        for (int n = 0; n < NN; n++) {
            float2 v = __bfloat1622float2(vf[n * (DD / 2)]);
            cx += alphas[n] * v.x;
            cy += alphas[n] * v.y;
        }
        cx += g_H[(size_t)r * DD + d];
        cy += g_H[(size_t)r * DD + d + 1];
        reinterpret_cast<bf162*>(g_ctxH_bf + (size_t)r * DD + d)[0] =
            __floats2bfloat162_rn(cx, cy);
    }
}

__global__ void logsoftmax_kernel(float* __restrict__ out)
{
    int r = blockIdx.x;
    int t = r / BB, b = r % BB;
    const float4* row = reinterpret_cast<const float4*>(g_logits + (size_t)r * VOC);
    const int NV = VOC / 4;
    __shared__ float red[512];
    float mx = -1e30f;
    for (int v = threadIdx.x; v < NV; v += 512) {
        float4 x = row[v];
        mx = fmaxf(mx, fmaxf(fmaxf(x.x, x.y), fmaxf(x.z, x.w)));
    }
    red[threadIdx.x] = mx; __syncthreads();
    for (int s = 256; s > 0; s >>= 1) {
        if (threadIdx.x < s) red[threadIdx.x] = fmaxf(red[threadIdx.x], red[threadIdx.x + s]);
        __syncthreads();
    }
    mx = red[0]; __syncthreads();
    float sum = 0.f;
    for (int v = threadIdx.x; v < NV; v += 512) {
        float4 x = row[v];
        sum += expf(x.x - mx) + expf(x.y - mx) + expf(x.z - mx) + expf(x.w - mx);
    }
    red[threadIdx.x] = sum; __syncthreads();
    for (int s = 256; s > 0; s >>= 1) {
        if (threadIdx.x < s) red[threadIdx.x] += red[threadIdx.x + s];
        __syncthreads();
    }
    float lse = mx + logf(red[0]);
    float4* orow = reinterpret_cast<float4*>(out + ((size_t)b * TT + t) * VOC);
    for (int v = threadIdx.x; v < NV; v += 512) {
        float4 x = row[v];
        orow[v] = make_float4(x.x - lse, x.y - lse, x.z - lse, x.w - lse);
    }
}

// ==================== host ====================
static inline void tc(const bf16* A, int lda, const bf16* B, int ldb,
                      const float* bias, float* C, bf16* Cb, int ldc,
                      int Mtiles, int N, int K, int act,
                      const float* aux1 = nullptr, const float* aux2 = nullptr)
{
    dim3 grid((N + 127) / 128, Mtiles);
    gemm_bf<<<grid, 256, SMEM_MM>>>(A, lda, B, ldb, bias, C, Cb, ldc, N, K, act, aux1, aux2);
}

static inline void tc64(const bf16* A, int lda, const bf16* B, int ldb,
                        const float* bias, float* C, bf16* Cb, int ldc,
                        int Mtiles, int N, int K, int act)
{
    dim3 grid((N + 63) / 64, Mtiles);
    gemm_bf64<<<grid, 256, SMEM_MM64>>>(A, lda, B, ldb, bias, C, Cb, ldc, N, K, act);
}

extern "C" void kernel_launch(void* const* d_in, const int* in_sizes, int n_in,
                              void* d_out, int out_size)
{
    const float* image = (const float*)d_in[0];
    const int*   target = (const int*)d_in[1];
    const float* emb = (const float*)d_in[2];
    const float* Wa = (const float*)d_in[3];  const float* ba = (const float*)d_in[4];
    const float* Wb = (const float*)d_in[5];  const float* bb = (const float*)d_in[6];
    const float* Whi = (const float*)d_in[7]; const float* bhi = (const float*)d_in[8];
    const float* Wmi = (const float*)d_in[9]; const float* bmi = (const float*)d_in[10];
    const float* Wih = (const float*)d_in[11]; const float* bih = (const float*)d_in[12];
    const float* Whh = (const float*)d_in[13]; const float* bhh = (const float*)d_in[14];
    const float* Wv = (const float*)d_in[15];
    const float* Wg = (const float*)d_in[16];
    const float* wh = (const float*)d_in[17];
    const float* WH = (const float*)d_in[18];
    const float* Wx = (const float*)d_in[19];
    const float* Wh2 = (const float*)d_in[20];
    const float* Ws = (const float*)d_in[21];
    const float* Wc = (const float*)d_in[22]; const float* bc = (const float*)d_in[23];
    const float* Wfc = (const float*)d_in[24]; const float* bfc = (const float*)d_in[25];
    const float* Wp = (const float*)d_in[26]; const float* bp = (const float*)d_in[27];

    float* out = (float*)d_out;
    float* out_attn = out + (size_t)BB * TT * VOC;

    static int attr_set = 0;
    if (!attr_set) {
        cudaFuncSetAttribute(gemm_bf, cudaFuncAttributeMaxDynamicSharedMemorySize, SMEM_MM);
        cudaFuncSetAttribute(gemm_bf64, cudaFuncAttributeMaxDynamicSharedMemorySize, SMEM_MM64);
        attr_set = 1;
    }

    float *p_Vf, *p_zbase, *p_bcat, *p_vg, *p_m, *p_tm, *p_bsum, *p_xg, *p_xx, *p_gates;
    float *p_H, *p_s, *p_gH, *p_sWs, *p_out, *p_logits, *p_init;
    bf16 *pb_image, *pb_Wa, *pb_mean, *pb_Wcat, *pb_xcat, *pb_Wih, *pb_Wx, *pb_Whh;
    bf16 *pb_Wh2, *pb_WH, *pb_Wc, *pb_Wfc, *pb_Wp, *pb_Wg, *pb_Ws;
    bf16 *pb_hseq, *pb_a, *pb_ctxH, *pb_out, *pb_Vfb, *pb_H, *pb_s;
    cudaGetSymbolAddress((void**)&p_Vf, g_Vf);
    cudaGetSymbolAddress((void**)&p_zbase, g_zbase);
    cudaGetSymbolAddress((void**)&p_bcat, g_bcat);
    cudaGetSymbolAddress((void**)&p_init, g_init);
    cudaGetSymbolAddress((void**)&p_vg, g_vg);
    cudaGetSymbolAddress((void**)&p_m, g_m);
    cudaGetSymbolAddress((void**)&p_tm, g_tm);
    cudaGetSymbolAddress((void**)&p_bsum, g_bsum);
    cudaGetSymbolAddress((void**)&p_xg, g_xg);
    cudaGetSymbolAddress((void**)&p_xx, g_xx);
    cudaGetSymbolAddress((void**)&p_gates, g_gates);
    cudaGetSymbolAddress((void**)&p_H, g_H);
    cudaGetSymbolAddress((void**)&p_s, g_s);
    cudaGetSymbolAddress((void**)&p_gH, g_gH);
    cudaGetSymbolAddress((void**)&p_sWs, g_sWs);
    cudaGetSymbolAddress((void**)&p_out, g_out);
    cudaGetSymbolAddress((void**)&p_logits, g_logits);
    cudaGetSymbolAddress((void**)&pb_image, g_image_bf);
    cudaGetSymbolAddress((void**)&pb_Wa, g_Wa_bf);
    cudaGetSymbolAddress((void**)&pb_mean, g_mean_bf);
    cudaGetSymbolAddress((void**)&pb_Wcat, g_Wcat_bf);
    cudaGetSymbolAddress((void**)&pb_xcat, g_xcat_bf);
    cudaGetSymbolAddress((void**)&pb_Wih, g_Wih_bf);
    cudaGetSymbolAddress((void**)&pb_Wx, g_Wx_bf);
    cudaGetSymbolAddress((void**)&pb_Whh, g_Whh_bf);
    cudaGetSymbolAddress((void**)&pb_Wh2, g_Wh2_bf);
    cudaGetSymbolAddress((void**)&pb_WH, g_WH_bf);
    cudaGetSymbolAddress((void**)&pb_Wc, g_Wc_bf);
    cudaGetSymbolAddress((void**)&pb_Wfc, g_Wfc_bf);
    cudaGetSymbolAddress((void**)&pb_Wp, g_Wp_bf);
    cudaGetSymbolAddress((void**)&pb_Wg, g_Wg_bf);
    cudaGetSymbolAddress((void**)&pb_Ws, g_Ws_bf);
    cudaGetSymbolAddress((void**)&pb_hseq, g_hseq_bf);
    cudaGetSymbolAddress((void**)&pb_a, g_a_bf);
    cudaGetSymbolAddress((void**)&pb_ctxH, g_ctxH_bf);
    cudaGetSymbolAddress((void**)&pb_out, g_out_bf);
    cudaGetSymbolAddress((void**)&pb_Vfb, g_Vfb);
    cudaGetSymbolAddress((void**)&pb_H, g_H_bf);
    cudaGetSymbolAddress((void**)&pb_s, g_s_bf);

    // ---- conversions (single launch) ----
    {
        ConvSegs segs;
        const float* srcs[NSEG] = { image, Wa, Wih, Wx, Whh, Wh2, WH, Wc, Wfc, Wp, Wg, Ws };
        bf16* dsts[NSEG] = { pb_image, pb_Wa, pb_Wih, pb_Wx, pb_Whh, pb_Wh2, pb_WH,
                             pb_Wc, pb_Wfc, pb_Wp, pb_Wg, pb_Ws };
        int ns[NSEG] = { BB * NN * CC / 4, DD * CC / 4, 4 * DD * (DD + EE) / 4,
                         DD * (DD + EE) / 4, 4 * DD * DD / 4, DD * DD / 4, DD * DD / 4,
                         DD * DD / 4, DD * DD / 4, VOC * DD / 4, NN * DD / 4, NN * DD / 4 };
        int total4 = 0;
        for (int i = 0; i < NSEG; i++) { segs.src[i] = srcs[i]; segs.dst[i] = dsts[i]; segs.n4[i] = ns[i]; total4 += ns[i]; }
        f2bf_multi<<<(total4 + 255) / 256, 256>>>(segs, total4);
    }
    cat_bias3<<<(4 * DD + 255) / 256, 256>>>(bb, bhi, bmi, p_bcat, bih, bhh, p_bsum);

    // ---- precompute ----
    mean_kernel<<<(BB * CC + 255) / 256, 256>>>(image, pb_mean);
    tc(pb_image, CC, pb_Wa, CC, ba, p_Vf, pb_Vfb, DD, BB * NN / 128, DD, CC, 1);
    cat_w3<<<(3 * DD * CC + 255) / 256, 256>>>(Wb, Whi, Wmi, pb_Wcat);
    tc(pb_mean, CC, pb_Wcat, CC, p_bcat, p_init, nullptr, 3 * DD, 1, 3 * DD, CC, 1);
    split_init<<<(BB * DD + 255) / 256, 256>>>(p_vg, pb_hseq, p_m);
    {
        dim3 grid(1, 1, BB);
        gemm_nt<64, 64, 16, 4, 4><<<grid, 256>>>(p_Vf, DD, Wv, DD, p_zbase, NN,
                                                 NN, NN, DD,
                                                 (long long)NN * DD, 0, (long long)NN * NN);
    }
    xcat_build<<<(RR * (DD + EE) + 255) / 256, 256>>>(target, emb);
    tc(pb_xcat, DD + EE, pb_Wih, DD + EE, p_bsum, p_xg, nullptr, 4 * DD, RR / 128, 4 * DD, DD + EE, 0);
    tc(pb_xcat, DD + EE, pb_Wx, DD + EE, nullptr, p_xx, nullptr, DD, RR / 128, DD, DD + EE, 0);

    // ---- sequential recurrence: gates GEMM (BN=64, 32 CTAs) + elementwise ----
    for (int t = 0; t < TT; t++) {
        tc64(pb_hseq + (size_t)t * BB * DD, DD, pb_Whh, DD, nullptr, p_gates, nullptr,
             4 * DD, 1, 4 * DD, DD, 0);
        lstm_elem<<<(BB * DD + 255) / 256, 256>>>(p_xg + (size_t)t * BB * 4 * DD,
                                                  p_m,
                                                  pb_hseq + (size_t)(t + 1) * BB * DD,
                                                  p_tm + (size_t)t * BB * DD);
    }

    // ---- batched epilogue over RR rows ----
    const bf16* Hp = pb_hseq;
    const bf16* Hc = pb_hseq + (size_t)BB * DD;
    tc(Hp, DD, pb_Wh2, DD, nullptr, nullptr, pb_a, DD, RR / 128, DD, DD, 3, p_xx, p_tm);
    tc(Hc, DD, pb_WH, DD, nullptr, p_H, pb_H, DD, RR / 128, DD, DD, 1);
    tc(pb_a, DD, pb_Wc, DD, bc, p_s, pb_s, DD, RR / 128, DD, DD, 1);
    tc64(pb_H, DD, pb_Wg, DD, nullptr, p_gH, nullptr, NN, RR / 128, NN, DD, 0);
    tc64(pb_s, DD, pb_Ws, DD, nullptr, p_sWs, nullptr, NN, RR / 128, NN, DD, 0);
    attn_batched<<<RR, 256>>>(wh, out_attn);
    tc(pb_ctxH, DD, pb_Wfc, DD, bfc, p_out, pb_out, DD, RR / 128, DD, DD, 2);

    // ---- logits + log_softmax ----
    tc(pb_out, DD, pb_Wp, DD, bp, p_logits, nullptr, VOC, RR / 128, VOC, DD, 0);
    logsoftmax_kernel<<<RR, 512>>>(out);
}